// round 4
// baseline (speedup 1.0000x reference)
#include <cuda_runtime.h>
#include <cuda_bf16.h>
#include <math.h>

#define Nn     50000
#define F0     512
#define HH     128
#define CC     40
#define EE     800000
#define NCAT   256   // HH * 2 towers packed

// ---------------- scratch (static device globals; no allocation) ----------------
__device__ float g_Wcat[F0 * NCAT];          // [512,256] = W1 cols 0..127, W3 cols 128..255
__device__ float g_xw[Nn * NCAT];            // X @ [W1 | W3]
__device__ float g_h[2][Nn * HH];            // spmm accumulators -> relu'd hidden
__device__ float g_hw[2][Nn * CC];           // h @ W2 / W4
__device__ float g_o[2][Nn * CC];            // second spmm accumulators (init = bias)

// ---------------- pack W1,W3 into a single 512x256 B matrix ----------------
__global__ void pack_w_kernel(const float* __restrict__ W1, const float* __restrict__ W3) {
    int idx = blockIdx.x * blockDim.x + threadIdx.x;   // 512*256
    if (idx >= F0 * NCAT) return;
    int k = idx / NCAT, c = idx % NCAT;
    g_Wcat[idx] = (c < HH) ? W1[k * HH + c] : W3[k * HH + (c - HH)];
}

// ---------------- SGEMM: C[M x 256] = A[M x 512] @ g_Wcat ----------------
// BM=128, BN=128, BK=16, TM=TN=8, 256 threads
__global__ __launch_bounds__(256) void sgemm_kernel(const float* __restrict__ A, int M) {
    const int K = F0, Nc = NCAT;
    __shared__ float As[16][128];
    __shared__ float Bs[16][128];
    int tid = threadIdx.x;
    int br = blockIdx.x, bc = blockIdx.y;       // bc: 0..1
    int innerRowA = tid >> 2, innerColA = tid & 3;    // + stride 64
    int innerRowB = tid >> 5, innerColB = tid & 31;   // + stride 8
    int threadRow = tid >> 4, threadCol = tid & 15;

    float acc[8][8];
#pragma unroll
    for (int i = 0; i < 8; i++)
#pragma unroll
        for (int j = 0; j < 8; j++) acc[i][j] = 0.f;

    const float* Aptr = A + (size_t)br * 128 * K;
    const float* Bptr = g_Wcat + bc * 128;

    for (int k0 = 0; k0 < K; k0 += 16) {
#pragma unroll
        for (int i = 0; i < 2; i++) {
            int r = innerRowA + i * 64;
            int grow = br * 128 + r;
            float4 v = make_float4(0.f, 0.f, 0.f, 0.f);
            if (grow < M) v = *(const float4*)(Aptr + r * K + k0 + innerColA * 4);
            As[innerColA * 4 + 0][r] = v.x;
            As[innerColA * 4 + 1][r] = v.y;
            As[innerColA * 4 + 2][r] = v.z;
            As[innerColA * 4 + 3][r] = v.w;
        }
#pragma unroll
        for (int i = 0; i < 2; i++) {
            int r = innerRowB + i * 8;
            float4 v = *(const float4*)(Bptr + (k0 + r) * Nc + innerColB * 4);
            *(float4*)&Bs[r][innerColB * 4] = v;
        }
        __syncthreads();

        float regM[8], regN[8];
#pragma unroll
        for (int k = 0; k < 16; k++) {
#pragma unroll
            for (int i = 0; i < 8; i++) regM[i] = As[k][threadRow * 8 + i];
#pragma unroll
            for (int j = 0; j < 8; j++) regN[j] = Bs[k][threadCol * 8 + j];
#pragma unroll
            for (int i = 0; i < 8; i++)
#pragma unroll
                for (int j = 0; j < 8; j++) acc[i][j] += regM[i] * regN[j];
        }
        __syncthreads();
    }
#pragma unroll
    for (int i = 0; i < 8; i++) {
        int grow = br * 128 + threadRow * 8 + i;
        if (grow < M) {
            float* cp = g_xw + (size_t)grow * Nc + bc * 128 + threadCol * 8;
            *(float4*)(cp + 0) = make_float4(acc[i][0], acc[i][1], acc[i][2], acc[i][3]);
            *(float4*)(cp + 4) = make_float4(acc[i][4], acc[i][5], acc[i][6], acc[i][7]);
        }
    }
}

// ---------------- zero hidden accumulators ----------------
__global__ void zero_h_kernel() {
    int idx = blockIdx.x * blockDim.x + threadIdx.x;
    if (idx < 2 * Nn * HH) ((float*)g_h)[idx] = 0.f;
}

// ---------------- SpMM F=128: out[dst] += val * feat[src]  (4 feats/thread) ----------------
__global__ void spmm128_kernel(int tower, const int* __restrict__ ei, const float* __restrict__ ev) {
    int idx = blockIdx.x * blockDim.x + threadIdx.x;   // EE * 32
    if (idx >= EE * 32) return;
    int e = idx >> 5;
    int c = (idx & 31) * 4;
    int s = __ldg(ei + e);
    int d = __ldg(ei + EE + e);
    float v = __ldg(ev + e);
    const float4 f = *(const float4*)(g_xw + (size_t)s * NCAT + tower * HH + c);
    float* o = g_h[tower] + (size_t)d * HH + c;
    atomicAdd(o + 0, v * f.x);
    atomicAdd(o + 1, v * f.y);
    atomicAdd(o + 2, v * f.z);
    atomicAdd(o + 3, v * f.w);
}

// ---------------- relu(acc + b) in place for both towers ----------------
__global__ void relu_bias_kernel(const float* __restrict__ b1, const float* __restrict__ b3) {
    int idx = blockIdx.x * blockDim.x + threadIdx.x;
    if (idx >= 2 * Nn * HH) return;
    int t = idx / (Nn * HH);
    int rem = idx - t * (Nn * HH);
    int f = rem & (HH - 1);
    const float* b = t ? b3 : b1;
    float val = g_h[t][rem] + b[f];
    g_h[t][rem] = val > 0.f ? val : 0.f;
}

// ---------------- hw = h @ W  (128 -> 40) ----------------
__global__ __launch_bounds__(240) void gemm2_kernel(int tower, const float* __restrict__ W) {
    __shared__ float sW[HH * CC];   // 20 KB
    int tid = threadIdx.y * CC + threadIdx.x;
    for (int i = tid; i < HH * CC; i += 240) sW[i] = W[i];
    __syncthreads();
    int row = blockIdx.x * 6 + threadIdx.y;
    int col = threadIdx.x;
    if (row >= Nn) return;
    const float4* hr = (const float4*)(g_h[tower] + (size_t)row * HH);
    float acc = 0.f;
#pragma unroll
    for (int k4 = 0; k4 < HH / 4; k4++) {
        float4 hv = hr[k4];
        int k = k4 * 4;
        acc += hv.x * sW[(k + 0) * CC + col];
        acc += hv.y * sW[(k + 1) * CC + col];
        acc += hv.z * sW[(k + 2) * CC + col];
        acc += hv.w * sW[(k + 3) * CC + col];
    }
    g_hw[tower][(size_t)row * CC + col] = acc;
}

// ---------------- init o accumulators with bias ----------------
__global__ void init_o_kernel(const float* __restrict__ b2, const float* __restrict__ b4) {
    int idx = blockIdx.x * blockDim.x + threadIdx.x;
    if (idx >= 2 * Nn * CC) return;
    int t = idx / (Nn * CC);
    int rem = idx - t * (Nn * CC);
    int c = rem % CC;
    ((float*)g_o)[idx] = (t ? b4 : b2)[c];
}

// ---------------- SpMM F=40 ----------------
__global__ void spmm40_kernel(int tower, const int* __restrict__ ei, const float* __restrict__ ev) {
    int idx = blockIdx.x * blockDim.x + threadIdx.x;  // EE * 10
    if (idx >= EE * 10) return;
    int e = idx / 10;
    int c = (idx - e * 10) * 4;
    int s = __ldg(ei + e);
    int d = __ldg(ei + EE + e);
    float v = __ldg(ev + e);
    const float4 f = *(const float4*)(g_hw[tower] + (size_t)s * CC + c);
    float* o = g_o[tower] + (size_t)d * CC + c;
    atomicAdd(o + 0, v * f.x);
    atomicAdd(o + 1, v * f.y);
    atomicAdd(o + 2, v * f.z);
    atomicAdd(o + 3, v * f.w);
}

// ---------------- gated fusion + log_softmax; one warp per row ----------------
__global__ __launch_bounds__(256) void fuse_kernel(const float* __restrict__ Wl,
                                                   const float* __restrict__ bl,
                                                   float* __restrict__ out) {
    __shared__ float sWl[2 * CC * CC];   // 80x40 = 12.8 KB
    __shared__ float sbl[CC];
    __shared__ float scat[8][2 * CC];
    int tid = threadIdx.x;
    for (int i = tid; i < 2 * CC * CC; i += 256) sWl[i] = Wl[i];
    if (tid < CC) sbl[tid] = bl[tid];
    __syncthreads();

    int w = tid >> 5, lane = tid & 31;
    int row = blockIdx.x * 8 + w;
    if (row >= Nn) return;

    const float* o1 = g_o[0] + (size_t)row * CC;
    const float* o2 = g_o[1] + (size_t)row * CC;
    // load concatenated row [o1 | o2] into shared
    for (int j = lane; j < 2 * CC; j += 32)
        scat[w][j] = (j < CC) ? o1[j] : o2[j - CC];
    __syncwarp();

    // each lane owns col=lane (<32) and possibly col=32+lane (lane<8)
    float v0, v1 = -INFINITY;
    {
        int c = lane;
        float a = sbl[c];
#pragma unroll
        for (int j = 0; j < 2 * CC; j++) a += scat[w][j] * sWl[j * CC + c];
        float g = 1.f / (1.f + __expf(-a));
        v0 = g * scat[w][c] + (1.f - g) * scat[w][CC + c];
    }
    if (lane < 8) {
        int c = 32 + lane;
        float a = sbl[c];
#pragma unroll
        for (int j = 0; j < 2 * CC; j++) a += scat[w][j] * sWl[j * CC + c];
        float g = 1.f / (1.f + __expf(-a));
        v1 = g * scat[w][c] + (1.f - g) * scat[w][CC + c];
    }
    // warp logsumexp over 40 values
    float m = fmaxf(v0, v1);
#pragma unroll
    for (int o = 16; o > 0; o >>= 1) m = fmaxf(m, __shfl_xor_sync(0xffffffff, m, o));
    float s = expf(v0 - m) + (lane < 8 ? expf(v1 - m) : 0.f);
#pragma unroll
    for (int o = 16; o > 0; o >>= 1) s += __shfl_xor_sync(0xffffffff, s, o);
    float lse = m + logf(s);

    out[(size_t)row * CC + lane] = v0 - lse;
    if (lane < 8) out[(size_t)row * CC + 32 + lane] = v1 - lse;
}

// ---------------- launch ----------------
extern "C" void kernel_launch(void* const* d_in, const int* in_sizes, int n_in,
                              void* d_out, int out_size) {
    const float* x   = (const float*)d_in[0];
    const int*   ei1 = (const int*)  d_in[1];
    const float* ev1 = (const float*)d_in[2];
    const int*   ei2 = (const int*)  d_in[3];
    const float* ev2 = (const float*)d_in[4];
    const float* W1  = (const float*)d_in[5];
    const float* b1  = (const float*)d_in[6];
    const float* W2  = (const float*)d_in[7];
    const float* b2  = (const float*)d_in[8];
    const float* W3  = (const float*)d_in[9];
    const float* b3  = (const float*)d_in[10];
    const float* W4  = (const float*)d_in[11];
    const float* b4  = (const float*)d_in[12];
    const float* Wl  = (const float*)d_in[13];
    const float* bl  = (const float*)d_in[14];
    float* out = (float*)d_out;

    // 1. pack W
    pack_w_kernel<<<(F0 * NCAT + 255) / 256, 256>>>(W1, W3);
    // 2. big fused GEMM
    dim3 ggrid((Nn + 127) / 128, 2);
    sgemm_kernel<<<ggrid, 256>>>(x, Nn);
    // 3. zero hidden accumulators
    zero_h_kernel<<<(2 * Nn * HH + 255) / 256, 256>>>();
    // 4. SpMM layer 1, both towers
    spmm128_kernel<<<(EE * 32 + 255) / 256, 256>>>(0, ei1, ev1);
    spmm128_kernel<<<(EE * 32 + 255) / 256, 256>>>(1, ei2, ev2);
    // 5. relu + bias
    relu_bias_kernel<<<(2 * Nn * HH + 255) / 256, 256>>>(b1, b3);
    // 6. small GEMMs
    dim3 g2block(CC, 6);
    gemm2_kernel<<<(Nn + 5) / 6, g2block>>>(0, W2);
    gemm2_kernel<<<(Nn + 5) / 6, g2block>>>(1, W4);
    // 7. init o with bias
    init_o_kernel<<<(2 * Nn * CC + 255) / 256, 256>>>(b2, b4);
    // 8. SpMM layer 2
    spmm40_kernel<<<(EE * 10 + 255) / 256, 256>>>(0, ei1, ev1);
    spmm40_kernel<<<(EE * 10 + 255) / 256, 256>>>(1, ei2, ev2);
    // 9. gated fusion + log_softmax
    fuse_kernel<<<(Nn + 7) / 8, 256>>>(Wl, bl, out);
}

// round 5
// speedup vs baseline: 2.4749x; 2.4749x over previous
#include <cuda_runtime.h>
#include <cuda_bf16.h>
#include <math.h>

#define Nn     50000
#define F0     512
#define HH     128
#define CC     40
#define EE     800000
#define NCAT   256   // HH * 2 towers packed

// ---------------- scratch (static device globals; no allocation) ----------------
__device__ float g_Wcat[F0 * NCAT];          // [512,256] = W1 cols 0..127, W3 cols 128..255
__device__ float g_xw[Nn * NCAT];            // X @ [W1 | W3]
__device__ float g_h[2][Nn * HH];            // spmm accumulators -> relu'd hidden
__device__ float g_hw[2][Nn * CC];           // h @ W2 / W4
__device__ float g_o[2][Nn * CC];            // second spmm accumulators (init = bias)

__device__ __forceinline__ void red_add_v4(float* addr, float x, float y, float z, float w) {
    asm volatile("red.global.add.v4.f32 [%0], {%1, %2, %3, %4};"
                 :: "l"(addr), "f"(x), "f"(y), "f"(z), "f"(w) : "memory");
}

// ---------------- pack W1,W3 into a single 512x256 B matrix ----------------
__global__ void pack_w_kernel(const float* __restrict__ W1, const float* __restrict__ W3) {
    int idx = blockIdx.x * blockDim.x + threadIdx.x;   // 512*256
    if (idx >= F0 * NCAT) return;
    int k = idx / NCAT, c = idx % NCAT;
    g_Wcat[idx] = (c < HH) ? W1[k * HH + c] : W3[k * HH + (c - HH)];
}

// ---------------- SGEMM: C[M x 256] = A[M x 512] @ g_Wcat ----------------
// BM=128, BN=128, BK=16, TM=TN=8, 256 threads
__global__ __launch_bounds__(256) void sgemm_kernel(const float* __restrict__ A, int M) {
    const int K = F0, Nc = NCAT;
    __shared__ float As[16][128];
    __shared__ float Bs[16][128];
    int tid = threadIdx.x;
    int br = blockIdx.x, bc = blockIdx.y;       // bc: 0..1
    int innerRowA = tid >> 2, innerColA = tid & 3;    // + stride 64
    int innerRowB = tid >> 5, innerColB = tid & 31;   // + stride 8
    int threadRow = tid >> 4, threadCol = tid & 15;

    float acc[8][8];
#pragma unroll
    for (int i = 0; i < 8; i++)
#pragma unroll
        for (int j = 0; j < 8; j++) acc[i][j] = 0.f;

    const float* Aptr = A + (size_t)br * 128 * K;
    const float* Bptr = g_Wcat + bc * 128;

    for (int k0 = 0; k0 < K; k0 += 16) {
#pragma unroll
        for (int i = 0; i < 2; i++) {
            int r = innerRowA + i * 64;
            int grow = br * 128 + r;
            float4 v = make_float4(0.f, 0.f, 0.f, 0.f);
            if (grow < M) v = *(const float4*)(Aptr + r * K + k0 + innerColA * 4);
            As[innerColA * 4 + 0][r] = v.x;
            As[innerColA * 4 + 1][r] = v.y;
            As[innerColA * 4 + 2][r] = v.z;
            As[innerColA * 4 + 3][r] = v.w;
        }
#pragma unroll
        for (int i = 0; i < 2; i++) {
            int r = innerRowB + i * 8;
            float4 v = *(const float4*)(Bptr + (k0 + r) * Nc + innerColB * 4);
            *(float4*)&Bs[r][innerColB * 4] = v;
        }
        __syncthreads();

        float regM[8], regN[8];
#pragma unroll
        for (int k = 0; k < 16; k++) {
#pragma unroll
            for (int i = 0; i < 8; i++) regM[i] = As[k][threadRow * 8 + i];
#pragma unroll
            for (int j = 0; j < 8; j++) regN[j] = Bs[k][threadCol * 8 + j];
#pragma unroll
            for (int i = 0; i < 8; i++)
#pragma unroll
                for (int j = 0; j < 8; j++) acc[i][j] += regM[i] * regN[j];
        }
        __syncthreads();
    }
#pragma unroll
    for (int i = 0; i < 8; i++) {
        int grow = br * 128 + threadRow * 8 + i;
        if (grow < M) {
            float* cp = g_xw + (size_t)grow * Nc + bc * 128 + threadCol * 8;
            *(float4*)(cp + 0) = make_float4(acc[i][0], acc[i][1], acc[i][2], acc[i][3]);
            *(float4*)(cp + 4) = make_float4(acc[i][4], acc[i][5], acc[i][6], acc[i][7]);
        }
    }
}

// ---------------- zero hidden accumulators (vectorized) ----------------
__global__ void zero_h_kernel() {
    int idx = blockIdx.x * blockDim.x + threadIdx.x;
    if (idx < 2 * Nn * HH / 4)
        ((float4*)g_h)[idx] = make_float4(0.f, 0.f, 0.f, 0.f);
}

// ---------------- SpMM F=128: out[dst] += val * feat[src]; 1 warp/edge, red.v4 ----------------
// grid.y = tower
__global__ __launch_bounds__(256) void spmm128_kernel(const int* __restrict__ ei1, const float* __restrict__ ev1,
                                                      const int* __restrict__ ei2, const float* __restrict__ ev2) {
    int idx = blockIdx.x * blockDim.x + threadIdx.x;   // EE * 32
    if (idx >= EE * 32) return;
    int tower = blockIdx.y;
    const int*   ei = tower ? ei2 : ei1;
    const float* ev = tower ? ev2 : ev1;
    int e = idx >> 5;
    int c = (idx & 31) * 4;
    int s = __ldg(ei + e);
    int d = __ldg(ei + EE + e);
    float v = __ldg(ev + e);
    const float4 f = *(const float4*)(g_xw + (size_t)s * NCAT + tower * HH + c);
    float* o = g_h[tower] + (size_t)d * HH + c;
    red_add_v4(o, v * f.x, v * f.y, v * f.z, v * f.w);
}

// ---------------- relu(acc + b) in place for both towers (vectorized) ----------------
__global__ void relu_bias_kernel(const float* __restrict__ b1, const float* __restrict__ b3) {
    int idx = blockIdx.x * blockDim.x + threadIdx.x;   // over float4s
    if (idx >= 2 * Nn * HH / 4) return;
    int t = idx / (Nn * HH / 4);
    int rem = idx - t * (Nn * HH / 4);
    int f = (rem & (HH / 4 - 1)) * 4;
    const float* b = t ? b3 : b1;
    float4 bv = *(const float4*)(b + f);
    float4 val = ((float4*)g_h[t])[rem];
    val.x = fmaxf(val.x + bv.x, 0.f);
    val.y = fmaxf(val.y + bv.y, 0.f);
    val.z = fmaxf(val.z + bv.z, 0.f);
    val.w = fmaxf(val.w + bv.w, 0.f);
    ((float4*)g_h[t])[rem] = val;
}

// ---------------- hw = h @ W  (128 -> 40); grid.y = tower ----------------
__global__ __launch_bounds__(240) void gemm2_kernel(const float* __restrict__ W2, const float* __restrict__ W4) {
    __shared__ float sW[HH * CC];   // 20 KB
    int tower = blockIdx.y;
    const float* W = tower ? W4 : W2;
    int tid = threadIdx.y * CC + threadIdx.x;
    for (int i = tid; i < HH * CC; i += 240) sW[i] = W[i];
    __syncthreads();
    int row = blockIdx.x * 6 + threadIdx.y;
    int col = threadIdx.x;
    if (row >= Nn) return;
    const float4* hr = (const float4*)(g_h[tower] + (size_t)row * HH);
    float acc = 0.f;
#pragma unroll
    for (int k4 = 0; k4 < HH / 4; k4++) {
        float4 hv = hr[k4];
        int k = k4 * 4;
        acc += hv.x * sW[(k + 0) * CC + col];
        acc += hv.y * sW[(k + 1) * CC + col];
        acc += hv.z * sW[(k + 2) * CC + col];
        acc += hv.w * sW[(k + 3) * CC + col];
    }
    g_hw[tower][(size_t)row * CC + col] = acc;
}

// ---------------- init o accumulators with bias (vectorized, CC=40 -> 10 float4/row) ----------------
__global__ void init_o_kernel(const float* __restrict__ b2, const float* __restrict__ b4) {
    int idx = blockIdx.x * blockDim.x + threadIdx.x;   // over float4s
    if (idx >= 2 * Nn * CC / 4) return;
    int t = idx / (Nn * CC / 4);
    int rem = idx - t * (Nn * CC / 4);
    int c = (rem % (CC / 4)) * 4;
    const float* b = t ? b4 : b2;
    ((float4*)g_o)[idx] = *(const float4*)(b + c);
}

// ---------------- SpMM F=40: red.v4, 10 lanes/edge; grid.y = tower ----------------
__global__ __launch_bounds__(256) void spmm40_kernel(const int* __restrict__ ei1, const float* __restrict__ ev1,
                                                     const int* __restrict__ ei2, const float* __restrict__ ev2) {
    int idx = blockIdx.x * blockDim.x + threadIdx.x;  // EE * 10
    if (idx >= EE * 10) return;
    int tower = blockIdx.y;
    const int*   ei = tower ? ei2 : ei1;
    const float* ev = tower ? ev2 : ev1;
    int e = idx / 10;
    int c = (idx - e * 10) * 4;
    int s = __ldg(ei + e);
    int d = __ldg(ei + EE + e);
    float v = __ldg(ev + e);
    const float4 f = *(const float4*)(g_hw[tower] + (size_t)s * CC + c);
    float* o = g_o[tower] + (size_t)d * CC + c;
    red_add_v4(o, v * f.x, v * f.y, v * f.z, v * f.w);
}

// ---------------- gated fusion + log_softmax; one warp per row ----------------
__global__ __launch_bounds__(256) void fuse_kernel(const float* __restrict__ Wl,
                                                   const float* __restrict__ bl,
                                                   float* __restrict__ out) {
    __shared__ float sWl[2 * CC * CC];   // 80x40 = 12.8 KB
    __shared__ float sbl[CC];
    __shared__ float scat[8][2 * CC];
    int tid = threadIdx.x;
    for (int i = tid; i < 2 * CC * CC; i += 256) sWl[i] = Wl[i];
    if (tid < CC) sbl[tid] = bl[tid];
    __syncthreads();

    int w = tid >> 5, lane = tid & 31;
    int row = blockIdx.x * 8 + w;
    if (row >= Nn) return;

    const float* o1 = g_o[0] + (size_t)row * CC;
    const float* o2 = g_o[1] + (size_t)row * CC;
    for (int j = lane; j < 2 * CC; j += 32)
        scat[w][j] = (j < CC) ? o1[j] : o2[j - CC];
    __syncwarp();

    float v0, v1 = -INFINITY;
    {
        int c = lane;
        float a = sbl[c];
#pragma unroll
        for (int j = 0; j < 2 * CC; j++) a += scat[w][j] * sWl[j * CC + c];
        float g = 1.f / (1.f + __expf(-a));
        v0 = g * scat[w][c] + (1.f - g) * scat[w][CC + c];
    }
    if (lane < 8) {
        int c = 32 + lane;
        float a = sbl[c];
#pragma unroll
        for (int j = 0; j < 2 * CC; j++) a += scat[w][j] * sWl[j * CC + c];
        float g = 1.f / (1.f + __expf(-a));
        v1 = g * scat[w][c] + (1.f - g) * scat[w][CC + c];
    }
    float m = fmaxf(v0, v1);
#pragma unroll
    for (int o = 16; o > 0; o >>= 1) m = fmaxf(m, __shfl_xor_sync(0xffffffff, m, o));
    float s = expf(v0 - m) + (lane < 8 ? expf(v1 - m) : 0.f);
#pragma unroll
    for (int o = 16; o > 0; o >>= 1) s += __shfl_xor_sync(0xffffffff, s, o);
    float lse = m + logf(s);

    out[(size_t)row * CC + lane] = v0 - lse;
    if (lane < 8) out[(size_t)row * CC + 32 + lane] = v1 - lse;
}

// ---------------- launch ----------------
extern "C" void kernel_launch(void* const* d_in, const int* in_sizes, int n_in,
                              void* d_out, int out_size) {
    const float* x   = (const float*)d_in[0];
    const int*   ei1 = (const int*)  d_in[1];
    const float* ev1 = (const float*)d_in[2];
    const int*   ei2 = (const int*)  d_in[3];
    const float* ev2 = (const float*)d_in[4];
    const float* W1  = (const float*)d_in[5];
    const float* b1  = (const float*)d_in[6];
    const float* W2  = (const float*)d_in[7];
    const float* b2  = (const float*)d_in[8];
    const float* W3  = (const float*)d_in[9];
    const float* b3  = (const float*)d_in[10];
    const float* W4  = (const float*)d_in[11];
    const float* b4  = (const float*)d_in[12];
    const float* Wl  = (const float*)d_in[13];
    const float* bl  = (const float*)d_in[14];
    float* out = (float*)d_out;

    // 1. pack W
    pack_w_kernel<<<(F0 * NCAT + 255) / 256, 256>>>(W1, W3);
    // 2. big fused GEMM
    dim3 ggrid((Nn + 127) / 128, 2);
    sgemm_kernel<<<ggrid, 256>>>(x, Nn);
    // 3. zero hidden accumulators
    zero_h_kernel<<<(2 * Nn * HH / 4 + 255) / 256, 256>>>();
    // 4. SpMM layer 1, both towers in one launch (grid.y = tower)
    {
        dim3 g((EE * 32 + 255) / 256, 2);
        spmm128_kernel<<<g, 256>>>(ei1, ev1, ei2, ev2);
    }
    // 5. relu + bias
    relu_bias_kernel<<<(2 * Nn * HH / 4 + 255) / 256, 256>>>(b1, b3);
    // 6. small GEMMs, both towers
    {
        dim3 blk(CC, 6);
        dim3 g((Nn + 5) / 6, 2);
        gemm2_kernel<<<g, blk>>>(W2, W4);
    }
    // 7. init o with bias
    init_o_kernel<<<(2 * Nn * CC / 4 + 255) / 256, 256>>>(b2, b4);
    // 8. SpMM layer 2, both towers
    {
        dim3 g((EE * 10 + 255) / 256, 2);
        spmm40_kernel<<<g, 256>>>(ei1, ev1, ei2, ev2);
    }
    // 9. gated fusion + log_softmax
    fuse_kernel<<<(Nn + 7) / 8, 256>>>(Wl, bl, out);
}

// round 8
// speedup vs baseline: 2.9323x; 1.1848x over previous
#include <cuda_runtime.h>
#include <cuda_bf16.h>
#include <math.h>
#include <cstdint>

#define Nn     50000
#define F0     512
#define HH     128
#define CC     40
#define EE     800000
#define NCAT   256   // packed output cols: W1 -> 0..127, W3 -> 128..255

// ---------------- scratch (static device globals; no allocation) ----------------
__device__ __nv_bfloat16 g_Ahi[(size_t)Nn * F0];
__device__ __nv_bfloat16 g_Alo[(size_t)Nn * F0];
__device__ __nv_bfloat16 g_Bhi[NCAT * F0];   // [n][k] K-major (transposed Wcat)
__device__ __nv_bfloat16 g_Blo[NCAT * F0];
__device__ float g_xw[(size_t)Nn * NCAT];    // X @ [W1 | W3]
__device__ float g_h[2][Nn * HH];            // spmm accumulators (bias/relu fused downstream)
__device__ float g_hw[2][Nn * CC];           // h @ W2 / W4
__device__ float g_o[2][Nn * CC];            // second spmm accumulators (init = bias)

// ======================= helpers =======================
__device__ __forceinline__ uint32_t smem_to_u32(const void* p) {
    uint32_t a;
    asm("{ .reg .u64 t; cvta.to.shared.u64 t, %1; cvt.u32.u64 %0, t; }" : "=r"(a) : "l"(p));
    return a;
}
__device__ __forceinline__ void cp16(uint32_t dst, const void* src) {
    asm volatile("cp.async.cg.shared.global [%0], [%1], 16;" :: "r"(dst), "l"(src));
}
#define CP_COMMIT() asm volatile("cp.async.commit_group;" ::: "memory")
#define CP_WAIT(n)  asm volatile("cp.async.wait_group %0;" :: "n"(n) : "memory")

#define LDSM4(r0, r1, r2, r3, addr) \
    asm volatile("ldmatrix.sync.aligned.m8n8.x4.shared.b16 {%0,%1,%2,%3}, [%4];" \
                 : "=r"(r0), "=r"(r1), "=r"(r2), "=r"(r3) : "r"(addr))

#define MMA16816(d, a, b) \
    asm volatile("mma.sync.aligned.m16n8k16.row.col.f32.bf16.bf16.f32 " \
                 "{%0,%1,%2,%3}, {%4,%5,%6,%7}, {%8,%9}, {%0,%1,%2,%3};" \
                 : "+f"((d)[0]), "+f"((d)[1]), "+f"((d)[2]), "+f"((d)[3]) \
                 : "r"((a)[0]), "r"((a)[1]), "r"((a)[2]), "r"((a)[3]), \
                   "r"((b)[0]), "r"((b)[1]))

__device__ __forceinline__ void red_add_v4(float* addr, float x, float y, float z, float w) {
    asm volatile("red.global.add.v4.f32 [%0], {%1, %2, %3, %4};"
                 :: "l"(addr), "f"(x), "f"(y), "f"(z), "f"(w) : "memory");
}

// ---------------- pack W1,W3 transposed into bf16 hi/lo [NCAT][F0] ----------------
__global__ void pack_w_kernel(const float* __restrict__ W1, const float* __restrict__ W3) {
    int idx = blockIdx.x * blockDim.x + threadIdx.x;   // NCAT * F0, k fastest
    if (idx >= NCAT * F0) return;
    int n = idx >> 9, k = idx & (F0 - 1);
    float w = (n < HH) ? W1[k * HH + n] : W3[k * HH + (n - HH)];
    __nv_bfloat16 hi = __float2bfloat16_rn(w);
    g_Bhi[idx] = hi;
    g_Blo[idx] = __float2bfloat16_rn(w - __bfloat162float(hi));
}

// ---------------- convert X fp32 -> bf16 hi/lo ----------------
__global__ void convert_x_kernel(const float* __restrict__ x) {
    int idx = blockIdx.x * blockDim.x + threadIdx.x;   // Nn*F0/4 float4s
    if (idx >= Nn * F0 / 4) return;
    float4 v = ((const float4*)x)[idx];
    __nv_bfloat16 h0 = __float2bfloat16_rn(v.x), h1 = __float2bfloat16_rn(v.y);
    __nv_bfloat16 h2 = __float2bfloat16_rn(v.z), h3 = __float2bfloat16_rn(v.w);
    __nv_bfloat16 l0 = __float2bfloat16_rn(v.x - __bfloat162float(h0));
    __nv_bfloat16 l1 = __float2bfloat16_rn(v.y - __bfloat162float(h1));
    __nv_bfloat16 l2 = __float2bfloat16_rn(v.z - __bfloat162float(h2));
    __nv_bfloat16 l3 = __float2bfloat16_rn(v.w - __bfloat162float(h3));
    __nv_bfloat162 hp0 = __halves2bfloat162(h0, h1), hp1 = __halves2bfloat162(h2, h3);
    __nv_bfloat162 lp0 = __halves2bfloat162(l0, l1), lp1 = __halves2bfloat162(l2, l3);
    uint2 hu, lu;
    hu.x = *(uint32_t*)&hp0; hu.y = *(uint32_t*)&hp1;
    lu.x = *(uint32_t*)&lp0; lu.y = *(uint32_t*)&lp1;
    ((uint2*)g_Ahi)[idx] = hu;
    ((uint2*)g_Alo)[idx] = lu;
}

// ---------------- bf16 split GEMM via mma.sync: g_xw = A(hi+lo) @ B(hi+lo)^T ----------------
// CTA: 128M x 128N; 8 warps (4M x 2N); warp tile 32M x 64N.
// K chunks of 32, 3-stage cp.async pipeline.
// Smem rows padded to 40 bf16 (80B): ldmatrix phase bank-group perm 5n%8 -> conflict-free.
#define SROW     40
#define S_A_ELEM (128 * SROW)              // 5120 elems per matrix
#define S_STAGE  (4 * S_A_ELEM)            // Ahi | Alo | Bhi | Blo = 20480 elems
#define S_TOTAL_BYTES (3 * S_STAGE * 2)    // 122880 B
#define KCHUNK   32
#define NSTAGE   (F0 / KCHUNK)             // 16

__device__ __forceinline__ void issue_stage(uint32_t smem_u32, int br, int bc, int slot, int k0) {
    int t = threadIdx.x;
    int row = t >> 1, half = t & 1;
    int koff = half * 16;
    size_t arow = (size_t)min(br * 128 + row, Nn - 1);
    const __nv_bfloat16* gah = g_Ahi + arow * F0 + k0 + koff;
    const __nv_bfloat16* gal = g_Alo + arow * F0 + k0 + koff;
    size_t nrow = (size_t)(bc * 128 + row);
    const __nv_bfloat16* gbh = g_Bhi + nrow * F0 + k0 + koff;
    const __nv_bfloat16* gbl = g_Blo + nrow * F0 + k0 + koff;
    uint32_t base = smem_u32 + slot * (S_STAGE * 2);
    uint32_t d = base + (row * SROW + koff) * 2;
    cp16(d,                      gah);     cp16(d + 16,                      gah + 8);
    cp16(d + S_A_ELEM * 2,       gal);     cp16(d + S_A_ELEM * 2 + 16,       gal + 8);
    cp16(d + 2 * S_A_ELEM * 2,   gbh);     cp16(d + 2 * S_A_ELEM * 2 + 16,   gbh + 8);
    cp16(d + 3 * S_A_ELEM * 2,   gbl);     cp16(d + 3 * S_A_ELEM * 2 + 16,   gbl + 8);
}

__global__ void __launch_bounds__(256, 1) sgemm_bf16_kernel() {
    extern __shared__ char smem[];
    uint32_t smem_u32 = smem_to_u32(smem);
    int tid = threadIdx.x, lane = tid & 31, wid = tid >> 5;
    int wm = wid & 3, wn = wid >> 2;
    int br = blockIdx.x, bc = blockIdx.y;

    float acc[2][8][4];
#pragma unroll
    for (int i = 0; i < 2; i++)
#pragma unroll
        for (int j = 0; j < 8; j++)
#pragma unroll
            for (int q = 0; q < 4; q++) acc[i][j][q] = 0.f;

    // ldmatrix per-lane address components (byte offsets within a stage)
    int a_row  = wm * 32 + (lane & 15);
    int a_koff = (lane >> 4) * 8;
    int b_n    = wn * 64 + (lane & 7) + ((lane >> 4) << 3);
    int b_koff = ((lane >> 3) & 1) * 8;

    issue_stage(smem_u32, br, bc, 0, 0);
    CP_COMMIT();
    issue_stage(smem_u32, br, bc, 1, KCHUNK);
    CP_COMMIT();

    for (int i = 0; i < NSTAGE; i++) {
        if (i + 2 < NSTAGE) CP_WAIT(1); else CP_WAIT(0);
        __syncthreads();
        if (i + 2 < NSTAGE) {
            issue_stage(smem_u32, br, bc, (i + 2) % 3, (i + 2) * KCHUNK);
            CP_COMMIT();
        }
        uint32_t stage = smem_u32 + (i % 3) * (S_STAGE * 2);
#pragma unroll
        for (int kk = 0; kk < KCHUNK; kk += 16) {
            uint32_t ahi[2][4], alo[2][4];
#pragma unroll
            for (int t = 0; t < 2; t++) {
                uint32_t addr = stage + ((a_row + t * 16) * SROW + kk + a_koff) * 2;
                LDSM4(ahi[t][0], ahi[t][1], ahi[t][2], ahi[t][3], addr);
                LDSM4(alo[t][0], alo[t][1], alo[t][2], alo[t][3], addr + S_A_ELEM * 2);
            }
            uint32_t bhi[8][2], blo[8][2];
#pragma unroll
            for (int p = 0; p < 4; p++) {
                uint32_t addr = stage + (2 * S_A_ELEM + (b_n + p * 16) * SROW + kk + b_koff) * 2;
                uint32_t r0, r1, r2, r3;
                LDSM4(r0, r1, r2, r3, addr);
                bhi[2 * p][0] = r0; bhi[2 * p][1] = r1;
                bhi[2 * p + 1][0] = r2; bhi[2 * p + 1][1] = r3;
                LDSM4(r0, r1, r2, r3, addr + S_A_ELEM * 2);
                blo[2 * p][0] = r0; blo[2 * p][1] = r1;
                blo[2 * p + 1][0] = r2; blo[2 * p + 1][1] = r3;
            }
#pragma unroll
            for (int mt = 0; mt < 2; mt++)
#pragma unroll
                for (int nt = 0; nt < 8; nt++) {
                    MMA16816(acc[mt][nt], ahi[mt], bhi[nt]);
                    MMA16816(acc[mt][nt], ahi[mt], blo[nt]);
                    MMA16816(acc[mt][nt], alo[mt], bhi[nt]);
                }
        }
        __syncthreads();
    }

    // epilogue: direct stores
#pragma unroll
    for (int mt = 0; mt < 2; mt++) {
        int r0 = br * 128 + wm * 32 + mt * 16 + (lane >> 2);
        int r1 = r0 + 8;
#pragma unroll
        for (int nt = 0; nt < 8; nt++) {
            int col = bc * 128 + wn * 64 + nt * 8 + (lane & 3) * 2;
            if (r0 < Nn)
                *(float2*)(g_xw + (size_t)r0 * NCAT + col) = make_float2(acc[mt][nt][0], acc[mt][nt][1]);
            if (r1 < Nn)
                *(float2*)(g_xw + (size_t)r1 * NCAT + col) = make_float2(acc[mt][nt][2], acc[mt][nt][3]);
        }
    }
}

// ---------------- zero hidden accumulators (vectorized) ----------------
__global__ void zero_h_kernel() {
    int idx = blockIdx.x * blockDim.x + threadIdx.x;
    if (idx < 2 * Nn * HH / 4)
        ((float4*)g_h)[idx] = make_float4(0.f, 0.f, 0.f, 0.f);
}

// ---------------- SpMM F=128: 1 warp/edge, red.v4; grid.y = tower ----------------
__global__ __launch_bounds__(256) void spmm128_kernel(const int* __restrict__ ei1, const float* __restrict__ ev1,
                                                      const int* __restrict__ ei2, const float* __restrict__ ev2) {
    int idx = blockIdx.x * blockDim.x + threadIdx.x;   // EE * 32
    if (idx >= EE * 32) return;
    int tower = blockIdx.y;
    const int*   ei = tower ? ei2 : ei1;
    const float* ev = tower ? ev2 : ev1;
    int e = idx >> 5;
    int c = (idx & 31) * 4;
    int s = __ldg(ei + e);
    int d = __ldg(ei + EE + e);
    float v = __ldg(ev + e);
    const float4 f = *(const float4*)(g_xw + (size_t)s * NCAT + tower * HH + c);
    float* o = g_h[tower] + (size_t)d * HH + c;
    red_add_v4(o, v * f.x, v * f.y, v * f.z, v * f.w);
}

// ---------------- hw = relu(h + b) @ W  (128 -> 40); bias+relu fused; grid.y = tower ----------------
__global__ __launch_bounds__(240) void gemm2_kernel(const float* __restrict__ W2, const float* __restrict__ W4,
                                                    const float* __restrict__ b1, const float* __restrict__ b3) {
    __shared__ float sW[HH * CC];   // 20 KB
    __shared__ float sb[HH];
    int tower = blockIdx.y;
    const float* W  = tower ? W4 : W2;
    const float* bb = tower ? b3 : b1;
    int tid = threadIdx.y * CC + threadIdx.x;
    for (int i = tid; i < HH * CC; i += 240) sW[i] = W[i];
    if (tid < HH) sb[tid] = bb[tid];
    __syncthreads();
    int row = blockIdx.x * 6 + threadIdx.y;
    int col = threadIdx.x;
    if (row >= Nn) return;
    const float4* hr = (const float4*)(g_h[tower] + (size_t)row * HH);
    float acc = 0.f;
#pragma unroll
    for (int k4 = 0; k4 < HH / 4; k4++) {
        float4 hv = hr[k4];
        int k = k4 * 4;
        float h0 = fmaxf(hv.x + sb[k + 0], 0.f);
        float h1 = fmaxf(hv.y + sb[k + 1], 0.f);
        float h2 = fmaxf(hv.z + sb[k + 2], 0.f);
        float h3 = fmaxf(hv.w + sb[k + 3], 0.f);
        acc += h0 * sW[(k + 0) * CC + col];
        acc += h1 * sW[(k + 1) * CC + col];
        acc += h2 * sW[(k + 2) * CC + col];
        acc += h3 * sW[(k + 3) * CC + col];
    }
    g_hw[tower][(size_t)row * CC + col] = acc;
}

// ---------------- init o accumulators with bias (vectorized) ----------------
__global__ void init_o_kernel(const float* __restrict__ b2, const float* __restrict__ b4) {
    int idx = blockIdx.x * blockDim.x + threadIdx.x;   // over float4s
    if (idx >= 2 * Nn * CC / 4) return;
    int t = idx / (Nn * CC / 4);
    int rem = idx - t * (Nn * CC / 4);
    int c = (rem % (CC / 4)) * 4;
    const float* b = t ? b4 : b2;
    ((float4*)g_o)[idx] = *(const float4*)(b + c);
}

// ---------------- SpMM F=40: red.v4, 10 lanes/edge; grid.y = tower ----------------
__global__ __launch_bounds__(256) void spmm40_kernel(const int* __restrict__ ei1, const float* __restrict__ ev1,
                                                     const int* __restrict__ ei2, const float* __restrict__ ev2) {
    int idx = blockIdx.x * blockDim.x + threadIdx.x;  // EE * 10
    if (idx >= EE * 10) return;
    int tower = blockIdx.y;
    const int*   ei = tower ? ei2 : ei1;
    const float* ev = tower ? ev2 : ev1;
    int e = idx / 10;
    int c = (idx - e * 10) * 4;
    int s = __ldg(ei + e);
    int d = __ldg(ei + EE + e);
    float v = __ldg(ev + e);
    const float4 f = *(const float4*)(g_hw[tower] + (size_t)s * CC + c);
    float* o = g_o[tower] + (size_t)d * CC + c;
    red_add_v4(o, v * f.x, v * f.y, v * f.z, v * f.w);
}

// ---------------- gated fusion + log_softmax; one warp per row ----------------
__global__ __launch_bounds__(256) void fuse_kernel(const float* __restrict__ Wl,
                                                   const float* __restrict__ bl,
                                                   float* __restrict__ out) {
    __shared__ float sWl[2 * CC * CC];   // 80x40 = 12.8 KB
    __shared__ float sbl[CC];
    __shared__ float scat[8][2 * CC];
    int tid = threadIdx.x;
    for (int i = tid; i < 2 * CC * CC; i += 256) sWl[i] = Wl[i];
    if (tid < CC) sbl[tid] = bl[tid];
    __syncthreads();

    int w = tid >> 5, lane = tid & 31;
    int row = blockIdx.x * 8 + w;
    if (row >= Nn) return;

    const float* o1 = g_o[0] + (size_t)row * CC;
    const float* o2 = g_o[1] + (size_t)row * CC;
    for (int j = lane; j < 2 * CC; j += 32)
        scat[w][j] = (j < CC) ? o1[j] : o2[j - CC];
    __syncwarp();

    float v0, v1 = -INFINITY;
    {
        int c = lane;
        float a = sbl[c];
#pragma unroll
        for (int j = 0; j < 2 * CC; j++) a += scat[w][j] * sWl[j * CC + c];
        float g = 1.f / (1.f + __expf(-a));
        v0 = g * scat[w][c] + (1.f - g) * scat[w][CC + c];
    }
    if (lane < 8) {
        int c = 32 + lane;
        float a = sbl[c];
#pragma unroll
        for (int j = 0; j < 2 * CC; j++) a += scat[w][j] * sWl[j * CC + c];
        float g = 1.f / (1.f + __expf(-a));
        v1 = g * scat[w][c] + (1.f - g) * scat[w][CC + c];
    }
    float m = fmaxf(v0, v1);
#pragma unroll
    for (int o = 16; o > 0; o >>= 1) m = fmaxf(m, __shfl_xor_sync(0xffffffff, m, o));
    float s = expf(v0 - m) + (lane < 8 ? expf(v1 - m) : 0.f);
#pragma unroll
    for (int o = 16; o > 0; o >>= 1) s += __shfl_xor_sync(0xffffffff, s, o);
    float lse = m + logf(s);

    out[(size_t)row * CC + lane] = v0 - lse;
    if (lane < 8) out[(size_t)row * CC + 32 + lane] = v1 - lse;
}

// ---------------- launch ----------------
extern "C" void kernel_launch(void* const* d_in, const int* in_sizes, int n_in,
                              void* d_out, int out_size) {
    const float* x   = (const float*)d_in[0];
    const int*   ei1 = (const int*)  d_in[1];
    const float* ev1 = (const float*)d_in[2];
    const int*   ei2 = (const int*)  d_in[3];
    const float* ev2 = (const float*)d_in[4];
    const float* W1  = (const float*)d_in[5];
    const float* b1  = (const float*)d_in[6];
    const float* W2  = (const float*)d_in[7];
    const float* b2  = (const float*)d_in[8];
    const float* W3  = (const float*)d_in[9];
    const float* b3  = (const float*)d_in[10];
    const float* W4  = (const float*)d_in[11];
    const float* b4  = (const float*)d_in[12];
    const float* Wl  = (const float*)d_in[13];
    const float* bl  = (const float*)d_in[14];
    float* out = (float*)d_out;

    static bool attr_set = false;
    if (!attr_set) {
        cudaFuncSetAttribute(sgemm_bf16_kernel, cudaFuncAttributeMaxDynamicSharedMemorySize, S_TOTAL_BYTES);
        attr_set = true;
    }

    // 1. pack W (bf16 hi/lo, transposed to [N][K])
    pack_w_kernel<<<(NCAT * F0 + 255) / 256, 256>>>(W1, W3);
    // 2. convert X to bf16 hi/lo
    convert_x_kernel<<<(Nn * F0 / 4 + 255) / 256, 256>>>(x);
    // 3. tensor-core GEMM (2-term bf16 split via mma.sync)
    {
        dim3 g((Nn + 127) / 128, 2);
        sgemm_bf16_kernel<<<g, 256, S_TOTAL_BYTES>>>();
    }
    // 4. zero hidden accumulators
    zero_h_kernel<<<(2 * Nn * HH / 4 + 255) / 256, 256>>>();
    // 5. SpMM layer 1, both towers
    {
        dim3 g((EE * 32 + 255) / 256, 2);
        spmm128_kernel<<<g, 256>>>(ei1, ev1, ei2, ev2);
    }
    // 6. small GEMMs with fused bias+relu, both towers
    {
        dim3 blk(CC, 6);
        dim3 g((Nn + 5) / 6, 2);
        gemm2_kernel<<<g, blk>>>(W2, W4, b1, b3);
    }
    // 7. init o with bias
    init_o_kernel<<<(2 * Nn * CC / 4 + 255) / 256, 256>>>(b2, b4);
    // 8. SpMM layer 2, both towers
    {
        dim3 g((EE * 10 + 255) / 256, 2);
        spmm40_kernel<<<g, 256>>>(ei1, ev1, ei2, ev2);
    }
    // 9. gated fusion + log_softmax
    fuse_kernel<<<(Nn + 7) / 8, 256>>>(Wl, bl, out);
}

// round 9
// speedup vs baseline: 3.5008x; 1.1938x over previous
#include <cuda_runtime.h>
#include <cuda_bf16.h>
#include <math.h>
#include <cstdint>

#define Nn     50000
#define F0     512
#define HH     128
#define CC     40
#define EE     800000
#define NCAT   256   // packed output cols: W1 -> 0..127, W3 -> 128..255

// ---------------- scratch (static device globals; no allocation) ----------------
__device__ __nv_bfloat16 g_Ahi[(size_t)Nn * F0];
__device__ __nv_bfloat16 g_Alo[(size_t)Nn * F0];
__device__ __nv_bfloat16 g_Bhi[NCAT * F0];   // [n][k] K-major (transposed Wcat)
__device__ __nv_bfloat16 g_Blo[NCAT * F0];
__device__ float g_xw[(size_t)Nn * NCAT];    // X @ [W1 | W3]
__device__ float g_h[2][Nn * HH];            // relu(spmm + b) hidden
__device__ float g_hw[2][Nn * CC];           // h @ W2 / W4
__device__ float g_o[2][Nn * CC];            // spmm2 + bias
// CSR (dst-binned edges, reused by both spmm layers)
__device__ int   g_deg[2][Nn];               // degree -> cursor (reused)
__device__ int   g_off[2][Nn + 1];
__device__ int   g_esrc[2][EE];
__device__ float g_eval[2][EE];

// ======================= helpers =======================
__device__ __forceinline__ uint32_t smem_to_u32(const void* p) {
    uint32_t a;
    asm("{ .reg .u64 t; cvta.to.shared.u64 t, %1; cvt.u32.u64 %0, t; }" : "=r"(a) : "l"(p));
    return a;
}
__device__ __forceinline__ void cp16(uint32_t dst, const void* src) {
    asm volatile("cp.async.cg.shared.global [%0], [%1], 16;" :: "r"(dst), "l"(src));
}
#define CP_COMMIT() asm volatile("cp.async.commit_group;" ::: "memory")
#define CP_WAIT(n)  asm volatile("cp.async.wait_group %0;" :: "n"(n) : "memory")

#define LDSM4(r0, r1, r2, r3, addr) \
    asm volatile("ldmatrix.sync.aligned.m8n8.x4.shared.b16 {%0,%1,%2,%3}, [%4];" \
                 : "=r"(r0), "=r"(r1), "=r"(r2), "=r"(r3) : "r"(addr))

#define MMA16816(d, a, b) \
    asm volatile("mma.sync.aligned.m16n8k16.row.col.f32.bf16.bf16.f32 " \
                 "{%0,%1,%2,%3}, {%4,%5,%6,%7}, {%8,%9}, {%0,%1,%2,%3};" \
                 : "+f"((d)[0]), "+f"((d)[1]), "+f"((d)[2]), "+f"((d)[3]) \
                 : "r"((a)[0]), "r"((a)[1]), "r"((a)[2]), "r"((a)[3]), \
                   "r"((b)[0]), "r"((b)[1]))

// ---------------- pack W1,W3 transposed into bf16 hi/lo [NCAT][F0] ----------------
__global__ void pack_w_kernel(const float* __restrict__ W1, const float* __restrict__ W3) {
    int idx = blockIdx.x * blockDim.x + threadIdx.x;   // NCAT * F0, k fastest
    if (idx >= NCAT * F0) return;
    int n = idx >> 9, k = idx & (F0 - 1);
    float w = (n < HH) ? W1[k * HH + n] : W3[k * HH + (n - HH)];
    __nv_bfloat16 hi = __float2bfloat16_rn(w);
    g_Bhi[idx] = hi;
    g_Blo[idx] = __float2bfloat16_rn(w - __bfloat162float(hi));
}

// ---------------- convert X fp32 -> bf16 hi/lo ----------------
__global__ void convert_x_kernel(const float* __restrict__ x) {
    int idx = blockIdx.x * blockDim.x + threadIdx.x;   // Nn*F0/4 float4s
    if (idx >= Nn * F0 / 4) return;
    float4 v = ((const float4*)x)[idx];
    __nv_bfloat16 h0 = __float2bfloat16_rn(v.x), h1 = __float2bfloat16_rn(v.y);
    __nv_bfloat16 h2 = __float2bfloat16_rn(v.z), h3 = __float2bfloat16_rn(v.w);
    __nv_bfloat16 l0 = __float2bfloat16_rn(v.x - __bfloat162float(h0));
    __nv_bfloat16 l1 = __float2bfloat16_rn(v.y - __bfloat162float(h1));
    __nv_bfloat16 l2 = __float2bfloat16_rn(v.z - __bfloat162float(h2));
    __nv_bfloat16 l3 = __float2bfloat16_rn(v.w - __bfloat162float(h3));
    __nv_bfloat162 hp0 = __halves2bfloat162(h0, h1), hp1 = __halves2bfloat162(h2, h3);
    __nv_bfloat162 lp0 = __halves2bfloat162(l0, l1), lp1 = __halves2bfloat162(l2, l3);
    uint2 hu, lu;
    hu.x = *(uint32_t*)&hp0; hu.y = *(uint32_t*)&hp1;
    lu.x = *(uint32_t*)&lp0; lu.y = *(uint32_t*)&lp1;
    ((uint2*)g_Ahi)[idx] = hu;
    ((uint2*)g_Alo)[idx] = lu;
}

// ---------------- bf16 split GEMM via mma.sync (unchanged from R8) ----------------
#define SROW     40
#define S_A_ELEM (128 * SROW)
#define S_STAGE  (4 * S_A_ELEM)
#define S_TOTAL_BYTES (3 * S_STAGE * 2)
#define KCHUNK   32
#define NSTAGE   (F0 / KCHUNK)

__device__ __forceinline__ void issue_stage(uint32_t smem_u32, int br, int bc, int slot, int k0) {
    int t = threadIdx.x;
    int row = t >> 1, half = t & 1;
    int koff = half * 16;
    size_t arow = (size_t)min(br * 128 + row, Nn - 1);
    const __nv_bfloat16* gah = g_Ahi + arow * F0 + k0 + koff;
    const __nv_bfloat16* gal = g_Alo + arow * F0 + k0 + koff;
    size_t nrow = (size_t)(bc * 128 + row);
    const __nv_bfloat16* gbh = g_Bhi + nrow * F0 + k0 + koff;
    const __nv_bfloat16* gbl = g_Blo + nrow * F0 + k0 + koff;
    uint32_t base = smem_u32 + slot * (S_STAGE * 2);
    uint32_t d = base + (row * SROW + koff) * 2;
    cp16(d,                      gah);     cp16(d + 16,                      gah + 8);
    cp16(d + S_A_ELEM * 2,       gal);     cp16(d + S_A_ELEM * 2 + 16,       gal + 8);
    cp16(d + 2 * S_A_ELEM * 2,   gbh);     cp16(d + 2 * S_A_ELEM * 2 + 16,   gbh + 8);
    cp16(d + 3 * S_A_ELEM * 2,   gbl);     cp16(d + 3 * S_A_ELEM * 2 + 16,   gbl + 8);
}

__global__ void __launch_bounds__(256, 1) sgemm_bf16_kernel() {
    extern __shared__ char smem[];
    uint32_t smem_u32 = smem_to_u32(smem);
    int tid = threadIdx.x, lane = tid & 31, wid = tid >> 5;
    int wm = wid & 3, wn = wid >> 2;
    int br = blockIdx.x, bc = blockIdx.y;

    float acc[2][8][4];
#pragma unroll
    for (int i = 0; i < 2; i++)
#pragma unroll
        for (int j = 0; j < 8; j++)
#pragma unroll
            for (int q = 0; q < 4; q++) acc[i][j][q] = 0.f;

    int a_row  = wm * 32 + (lane & 15);
    int a_koff = (lane >> 4) * 8;
    int b_n    = wn * 64 + (lane & 7) + ((lane >> 4) << 3);
    int b_koff = ((lane >> 3) & 1) * 8;

    issue_stage(smem_u32, br, bc, 0, 0);
    CP_COMMIT();
    issue_stage(smem_u32, br, bc, 1, KCHUNK);
    CP_COMMIT();

    for (int i = 0; i < NSTAGE; i++) {
        if (i + 2 < NSTAGE) CP_WAIT(1); else CP_WAIT(0);
        __syncthreads();
        if (i + 2 < NSTAGE) {
            issue_stage(smem_u32, br, bc, (i + 2) % 3, (i + 2) * KCHUNK);
            CP_COMMIT();
        }
        uint32_t stage = smem_u32 + (i % 3) * (S_STAGE * 2);
#pragma unroll
        for (int kk = 0; kk < KCHUNK; kk += 16) {
            uint32_t ahi[2][4], alo[2][4];
#pragma unroll
            for (int t = 0; t < 2; t++) {
                uint32_t addr = stage + ((a_row + t * 16) * SROW + kk + a_koff) * 2;
                LDSM4(ahi[t][0], ahi[t][1], ahi[t][2], ahi[t][3], addr);
                LDSM4(alo[t][0], alo[t][1], alo[t][2], alo[t][3], addr + S_A_ELEM * 2);
            }
            uint32_t bhi[8][2], blo[8][2];
#pragma unroll
            for (int p = 0; p < 4; p++) {
                uint32_t addr = stage + (2 * S_A_ELEM + (b_n + p * 16) * SROW + kk + b_koff) * 2;
                uint32_t r0, r1, r2, r3;
                LDSM4(r0, r1, r2, r3, addr);
                bhi[2 * p][0] = r0; bhi[2 * p][1] = r1;
                bhi[2 * p + 1][0] = r2; bhi[2 * p + 1][1] = r3;
                LDSM4(r0, r1, r2, r3, addr + S_A_ELEM * 2);
                blo[2 * p][0] = r0; blo[2 * p][1] = r1;
                blo[2 * p + 1][0] = r2; blo[2 * p + 1][1] = r3;
            }
#pragma unroll
            for (int mt = 0; mt < 2; mt++)
#pragma unroll
                for (int nt = 0; nt < 8; nt++) {
                    MMA16816(acc[mt][nt], ahi[mt], bhi[nt]);
                    MMA16816(acc[mt][nt], ahi[mt], blo[nt]);
                    MMA16816(acc[mt][nt], alo[mt], bhi[nt]);
                }
        }
        __syncthreads();
    }

#pragma unroll
    for (int mt = 0; mt < 2; mt++) {
        int r0 = br * 128 + wm * 32 + mt * 16 + (lane >> 2);
        int r1 = r0 + 8;
#pragma unroll
        for (int nt = 0; nt < 8; nt++) {
            int col = bc * 128 + wn * 64 + nt * 8 + (lane & 3) * 2;
            if (r0 < Nn)
                *(float2*)(g_xw + (size_t)r0 * NCAT + col) = make_float2(acc[mt][nt][0], acc[mt][nt][1]);
            if (r1 < Nn)
                *(float2*)(g_xw + (size_t)r1 * NCAT + col) = make_float2(acc[mt][nt][2], acc[mt][nt][3]);
        }
    }
}

// ================= CSR build (per tower; reused by both spmm layers) =================
__global__ void zero_deg_kernel() {
    int idx = blockIdx.x * blockDim.x + threadIdx.x;
    if (idx < 2 * Nn) ((int*)g_deg)[idx] = 0;
}

__global__ void hist_kernel(const int* __restrict__ ei1, const int* __restrict__ ei2) {
    int idx = blockIdx.x * blockDim.x + threadIdx.x;
    if (idx >= 2 * EE) return;
    int t = idx >= EE;
    int e = t ? idx - EE : idx;
    const int* ei = t ? ei2 : ei1;
    atomicAdd(&g_deg[t][__ldg(ei + EE + e)], 1);
}

// one block per tower; 1024 threads, each owns a contiguous chunk of rows
__global__ __launch_bounds__(1024) void scan_kernel() {
    int t = blockIdx.x;
    int tid = threadIdx.x, lane = tid & 31, wid = tid >> 5;
    const int CH = (Nn + 1023) / 1024;   // 49
    int base = tid * CH;
    int hi = min(base + CH, Nn);
    int sum = 0;
    for (int i = base; i < hi; i++) sum += g_deg[t][i];
    // block-wide exclusive scan of per-thread sums
    int x = sum;
#pragma unroll
    for (int o = 1; o < 32; o <<= 1) {
        int y = __shfl_up_sync(0xffffffff, x, o);
        if (lane >= o) x += y;
    }
    __shared__ int wsum[32];
    if (lane == 31) wsum[wid] = x;
    __syncthreads();
    if (wid == 0) {
        int z = wsum[lane];
#pragma unroll
        for (int o = 1; o < 32; o <<= 1) {
            int y = __shfl_up_sync(0xffffffff, z, o);
            if (lane >= o) z += y;
        }
        wsum[lane] = z;
    }
    __syncthreads();
    int incl = x + (wid > 0 ? wsum[wid - 1] : 0);
    int run = incl - sum;   // exclusive base for this thread
    for (int i = base; i < hi; i++) {
        int d = g_deg[t][i];
        g_off[t][i] = run;
        g_deg[t][i] = run;   // becomes scatter cursor
        run += d;
    }
    if (tid == 1023) g_off[t][Nn] = incl;
}

__global__ void scatter_kernel(const int* __restrict__ ei1, const float* __restrict__ ev1,
                               const int* __restrict__ ei2, const float* __restrict__ ev2) {
    int idx = blockIdx.x * blockDim.x + threadIdx.x;
    if (idx >= 2 * EE) return;
    int t = idx >= EE;
    int e = t ? idx - EE : idx;
    const int* ei = t ? ei2 : ei1;
    const float* ev = t ? ev2 : ev1;
    int src = __ldg(ei + e);
    int dst = __ldg(ei + EE + e);
    int pos = atomicAdd(&g_deg[t][dst], 1);
    g_esrc[t][pos] = src;
    g_eval[t][pos] = __ldg(ev + e);
}

// ---------------- CSR SpMM F=128: h = relu(sum + b); 32 threads/row ----------------
__global__ __launch_bounds__(256) void spmm_csr128_kernel(const float* __restrict__ b1,
                                                          const float* __restrict__ b3) {
    int idx = blockIdx.x * blockDim.x + threadIdx.x;   // Nn * 32
    if (idx >= Nn * 32) return;
    int t = blockIdx.y;
    int row = idx >> 5;
    int c = (idx & 31) * 4;
    int s0 = __ldg(&g_off[t][row]), s1 = __ldg(&g_off[t][row + 1]);
    const int*   es = g_esrc[t];
    const float* evv = g_eval[t];
    const float* feat = g_xw + t * HH + c;
    float ax = 0.f, ay = 0.f, az = 0.f, aw = 0.f;
    int e = s0;
    for (; e + 2 <= s1; e += 2) {
        int   sA = __ldg(es + e),     sB = __ldg(es + e + 1);
        float vA = __ldg(evv + e),    vB = __ldg(evv + e + 1);
        float4 fA = *(const float4*)(feat + (size_t)sA * NCAT);
        float4 fB = *(const float4*)(feat + (size_t)sB * NCAT);
        ax += vA * fA.x + vB * fB.x;
        ay += vA * fA.y + vB * fB.y;
        az += vA * fA.z + vB * fB.z;
        aw += vA * fA.w + vB * fB.w;
    }
    if (e < s1) {
        int   sA = __ldg(es + e);
        float vA = __ldg(evv + e);
        float4 fA = *(const float4*)(feat + (size_t)sA * NCAT);
        ax += vA * fA.x; ay += vA * fA.y; az += vA * fA.z; aw += vA * fA.w;
    }
    const float* b = t ? b3 : b1;
    float4 bv = *(const float4*)(b + c);
    float4 r;
    r.x = fmaxf(ax + bv.x, 0.f);
    r.y = fmaxf(ay + bv.y, 0.f);
    r.z = fmaxf(az + bv.z, 0.f);
    r.w = fmaxf(aw + bv.w, 0.f);
    *(float4*)(g_h[t] + (size_t)row * HH + c) = r;
}

// ---------------- hw = h @ W  (128 -> 40); h already relu'd; grid.y = tower ----------------
__global__ __launch_bounds__(240) void gemm2_kernel(const float* __restrict__ W2, const float* __restrict__ W4) {
    __shared__ float sW[HH * CC];   // 20 KB
    int tower = blockIdx.y;
    const float* W = tower ? W4 : W2;
    int tid = threadIdx.y * CC + threadIdx.x;
    for (int i = tid; i < HH * CC; i += 240) sW[i] = W[i];
    __syncthreads();
    int row = blockIdx.x * 6 + threadIdx.y;
    int col = threadIdx.x;
    if (row >= Nn) return;
    const float4* hr = (const float4*)(g_h[tower] + (size_t)row * HH);
    float acc = 0.f;
#pragma unroll
    for (int k4 = 0; k4 < HH / 4; k4++) {
        float4 hv = hr[k4];
        int k = k4 * 4;
        acc += hv.x * sW[(k + 0) * CC + col];
        acc += hv.y * sW[(k + 1) * CC + col];
        acc += hv.z * sW[(k + 2) * CC + col];
        acc += hv.w * sW[(k + 3) * CC + col];
    }
    g_hw[tower][(size_t)row * CC + col] = acc;
}

// ---------------- CSR SpMM F=40: o = sum + b; 10 threads/row ----------------
__global__ __launch_bounds__(250) void spmm_csr40_kernel(const float* __restrict__ b2,
                                                         const float* __restrict__ b4) {
    int idx = blockIdx.x * blockDim.x + threadIdx.x;   // Nn * 10
    if (idx >= Nn * 10) return;
    int t = blockIdx.y;
    int row = idx / 10;
    int c = (idx - row * 10) * 4;
    int s0 = __ldg(&g_off[t][row]), s1 = __ldg(&g_off[t][row + 1]);
    const int*   es = g_esrc[t];
    const float* evv = g_eval[t];
    const float* feat = g_hw[t] + c;
    float ax = 0.f, ay = 0.f, az = 0.f, aw = 0.f;
    int e = s0;
    for (; e + 2 <= s1; e += 2) {
        int   sA = __ldg(es + e),     sB = __ldg(es + e + 1);
        float vA = __ldg(evv + e),    vB = __ldg(evv + e + 1);
        float4 fA = *(const float4*)(feat + (size_t)sA * CC);
        float4 fB = *(const float4*)(feat + (size_t)sB * CC);
        ax += vA * fA.x + vB * fB.x;
        ay += vA * fA.y + vB * fB.y;
        az += vA * fA.z + vB * fB.z;
        aw += vA * fA.w + vB * fB.w;
    }
    if (e < s1) {
        int   sA = __ldg(es + e);
        float vA = __ldg(evv + e);
        float4 fA = *(const float4*)(feat + (size_t)sA * CC);
        ax += vA * fA.x; ay += vA * fA.y; az += vA * fA.z; aw += vA * fA.w;
    }
    const float* b = t ? b4 : b2;
    float* o = g_o[t] + (size_t)row * CC + c;
    o[0] = ax + b[c];
    o[1] = ay + b[c + 1];
    o[2] = az + b[c + 2];
    o[3] = aw + b[c + 3];
}

// ---------------- gated fusion + log_softmax; one warp per row ----------------
__global__ __launch_bounds__(256) void fuse_kernel(const float* __restrict__ Wl,
                                                   const float* __restrict__ bl,
                                                   float* __restrict__ out) {
    __shared__ float sWl[2 * CC * CC];   // 80x40 = 12.8 KB
    __shared__ float sbl[CC];
    __shared__ float scat[8][2 * CC];
    int tid = threadIdx.x;
    for (int i = tid; i < 2 * CC * CC; i += 256) sWl[i] = Wl[i];
    if (tid < CC) sbl[tid] = bl[tid];
    __syncthreads();

    int w = tid >> 5, lane = tid & 31;
    int row = blockIdx.x * 8 + w;
    if (row >= Nn) return;

    const float* o1 = g_o[0] + (size_t)row * CC;
    const float* o2 = g_o[1] + (size_t)row * CC;
    for (int j = lane; j < 2 * CC; j += 32)
        scat[w][j] = (j < CC) ? o1[j] : o2[j - CC];
    __syncwarp();

    float v0, v1 = -INFINITY;
    {
        int c = lane;
        float a = sbl[c];
#pragma unroll
        for (int j = 0; j < 2 * CC; j++) a += scat[w][j] * sWl[j * CC + c];
        float g = 1.f / (1.f + __expf(-a));
        v0 = g * scat[w][c] + (1.f - g) * scat[w][CC + c];
    }
    if (lane < 8) {
        int c = 32 + lane;
        float a = sbl[c];
#pragma unroll
        for (int j = 0; j < 2 * CC; j++) a += scat[w][j] * sWl[j * CC + c];
        float g = 1.f / (1.f + __expf(-a));
        v1 = g * scat[w][c] + (1.f - g) * scat[w][CC + c];
    }
    float m = fmaxf(v0, v1);
#pragma unroll
    for (int o = 16; o > 0; o >>= 1) m = fmaxf(m, __shfl_xor_sync(0xffffffff, m, o));
    float s = expf(v0 - m) + (lane < 8 ? expf(v1 - m) : 0.f);
#pragma unroll
    for (int o = 16; o > 0; o >>= 1) s += __shfl_xor_sync(0xffffffff, s, o);
    float lse = m + logf(s);

    out[(size_t)row * CC + lane] = v0 - lse;
    if (lane < 8) out[(size_t)row * CC + 32 + lane] = v1 - lse;
}

// ---------------- launch ----------------
extern "C" void kernel_launch(void* const* d_in, const int* in_sizes, int n_in,
                              void* d_out, int out_size) {
    const float* x   = (const float*)d_in[0];
    const int*   ei1 = (const int*)  d_in[1];
    const float* ev1 = (const float*)d_in[2];
    const int*   ei2 = (const int*)  d_in[3];
    const float* ev2 = (const float*)d_in[4];
    const float* W1  = (const float*)d_in[5];
    const float* b1  = (const float*)d_in[6];
    const float* W2  = (const float*)d_in[7];
    const float* b2  = (const float*)d_in[8];
    const float* W3  = (const float*)d_in[9];
    const float* b3  = (const float*)d_in[10];
    const float* W4  = (const float*)d_in[11];
    const float* b4  = (const float*)d_in[12];
    const float* Wl  = (const float*)d_in[13];
    const float* bl  = (const float*)d_in[14];
    float* out = (float*)d_out;

    static bool attr_set = false;
    if (!attr_set) {
        cudaFuncSetAttribute(sgemm_bf16_kernel, cudaFuncAttributeMaxDynamicSharedMemorySize, S_TOTAL_BYTES);
        attr_set = true;
    }

    // CSR build (independent of GEMM chain)
    zero_deg_kernel<<<(2 * Nn + 255) / 256, 256>>>();
    hist_kernel<<<(2 * EE + 255) / 256, 256>>>(ei1, ei2);
    scan_kernel<<<2, 1024>>>();
    scatter_kernel<<<(2 * EE + 255) / 256, 256>>>(ei1, ev1, ei2, ev2);

    // dense chain
    pack_w_kernel<<<(NCAT * F0 + 255) / 256, 256>>>(W1, W3);
    convert_x_kernel<<<(Nn * F0 / 4 + 255) / 256, 256>>>(x);
    {
        dim3 g((Nn + 127) / 128, 2);
        sgemm_bf16_kernel<<<g, 256, S_TOTAL_BYTES>>>();
    }
    // SpMM layer 1 (CSR, fused bias+relu), both towers
    {
        dim3 g((Nn * 32 + 255) / 256, 2);
        spmm_csr128_kernel<<<g, 256>>>(b1, b3);
    }
    // small GEMMs
    {
        dim3 blk(CC, 6);
        dim3 g((Nn + 5) / 6, 2);
        gemm2_kernel<<<g, blk>>>(W2, W4);
    }
    // SpMM layer 2 (CSR, fused bias), both towers
    {
        dim3 g((Nn * 10 + 249) / 250, 2);
        spmm_csr40_kernel<<<g, 250>>>(b2, b4);
    }
    // gated fusion + log_softmax
    fuse_kernel<<<(Nn + 7) / 8, 256>>>(Wl, bl, out);
}

// round 11
// speedup vs baseline: 3.9060x; 1.1158x over previous
#include <cuda_runtime.h>
#include <cuda_bf16.h>
#include <math.h>
#include <cstdint>

#define Nn     50000
#define F0     512
#define HH     128
#define CC     40
#define EE     800000
#define NCAT   256   // packed output cols: W1 -> 0..127, W3 -> 128..255

// ---------------- scratch (static device globals; no allocation) ----------------
__device__ __nv_bfloat16 g_Ahi[(size_t)Nn * F0];
__device__ __nv_bfloat16 g_Alo[(size_t)Nn * F0];
__device__ __nv_bfloat16 g_Bhi[NCAT * F0];   // [n][k] K-major (transposed Wcat)
__device__ __nv_bfloat16 g_Blo[NCAT * F0];
__device__ float g_xw[(size_t)Nn * NCAT];    // X @ [W1 | W3]
__device__ float g_h[2][Nn * HH];            // relu(spmm + b) hidden
__device__ float g_hw[2][Nn * CC];           // h @ W2 / W4
__device__ float g_o[2][Nn * CC];            // spmm2 + bias
// CSR (dst-binned edges, reused by both spmm layers)
__device__ int   g_deg[2][Nn];               // degree -> cursor (reused)
__device__ int   g_off[2][Nn + 1];
__device__ int   g_esrc[2][EE];
__device__ float g_eval[2][EE];

// ======================= helpers =======================
__device__ __forceinline__ uint32_t smem_to_u32(const void* p) {
    uint32_t a;
    asm("{ .reg .u64 t; cvta.to.shared.u64 t, %1; cvt.u32.u64 %0, t; }" : "=r"(a) : "l"(p));
    return a;
}
__device__ __forceinline__ void cp16(uint32_t dst, const void* src) {
    asm volatile("cp.async.cg.shared.global [%0], [%1], 16;" :: "r"(dst), "l"(src));
}
#define CP_COMMIT() asm volatile("cp.async.commit_group;" ::: "memory")
#define CP_WAIT(n)  asm volatile("cp.async.wait_group %0;" :: "n"(n) : "memory")

#define LDSM4(r0, r1, r2, r3, addr) \
    asm volatile("ldmatrix.sync.aligned.m8n8.x4.shared.b16 {%0,%1,%2,%3}, [%4];" \
                 : "=r"(r0), "=r"(r1), "=r"(r2), "=r"(r3) : "r"(addr))

#define MMA16816(d, a, b) \
    asm volatile("mma.sync.aligned.m16n8k16.row.col.f32.bf16.bf16.f32 " \
                 "{%0,%1,%2,%3}, {%4,%5,%6,%7}, {%8,%9}, {%0,%1,%2,%3};" \
                 : "+f"((d)[0]), "+f"((d)[1]), "+f"((d)[2]), "+f"((d)[3]) \
                 : "r"((a)[0]), "r"((a)[1]), "r"((a)[2]), "r"((a)[3]), \
                   "r"((b)[0]), "r"((b)[1]))

// ---------------- pack W1,W3 transposed into bf16 hi/lo [NCAT][F0] ----------------
__global__ void pack_w_kernel(const float* __restrict__ W1, const float* __restrict__ W3) {
    int idx = blockIdx.x * blockDim.x + threadIdx.x;   // NCAT * F0, k fastest
    if (idx >= NCAT * F0) return;
    int n = idx >> 9, k = idx & (F0 - 1);
    float w = (n < HH) ? W1[k * HH + n] : W3[k * HH + (n - HH)];
    __nv_bfloat16 hi = __float2bfloat16_rn(w);
    g_Bhi[idx] = hi;
    g_Blo[idx] = __float2bfloat16_rn(w - __bfloat162float(hi));
}

// ---------------- convert X fp32 -> bf16 hi/lo ----------------
__global__ void convert_x_kernel(const float* __restrict__ x) {
    int idx = blockIdx.x * blockDim.x + threadIdx.x;   // Nn*F0/4 float4s
    if (idx >= Nn * F0 / 4) return;
    float4 v = ((const float4*)x)[idx];
    __nv_bfloat16 h0 = __float2bfloat16_rn(v.x), h1 = __float2bfloat16_rn(v.y);
    __nv_bfloat16 h2 = __float2bfloat16_rn(v.z), h3 = __float2bfloat16_rn(v.w);
    __nv_bfloat16 l0 = __float2bfloat16_rn(v.x - __bfloat162float(h0));
    __nv_bfloat16 l1 = __float2bfloat16_rn(v.y - __bfloat162float(h1));
    __nv_bfloat16 l2 = __float2bfloat16_rn(v.z - __bfloat162float(h2));
    __nv_bfloat16 l3 = __float2bfloat16_rn(v.w - __bfloat162float(h3));
    __nv_bfloat162 hp0 = __halves2bfloat162(h0, h1), hp1 = __halves2bfloat162(h2, h3);
    __nv_bfloat162 lp0 = __halves2bfloat162(l0, l1), lp1 = __halves2bfloat162(l2, l3);
    uint2 hu, lu;
    hu.x = *(uint32_t*)&hp0; hu.y = *(uint32_t*)&hp1;
    lu.x = *(uint32_t*)&lp0; lu.y = *(uint32_t*)&lp1;
    ((uint2*)g_Ahi)[idx] = hu;
    ((uint2*)g_Alo)[idx] = lu;
}

// ---------------- bf16 split GEMM via mma.sync ----------------
#define SROW     40
#define S_A_ELEM (128 * SROW)
#define S_STAGE  (4 * S_A_ELEM)
#define S_TOTAL_BYTES (3 * S_STAGE * 2)
#define KCHUNK   32
#define NSTAGE   (F0 / KCHUNK)

__device__ __forceinline__ void issue_stage(uint32_t smem_u32, int br, int bc, int slot, int k0) {
    int t = threadIdx.x;
    int row = t >> 1, half = t & 1;
    int koff = half * 16;
    size_t arow = (size_t)min(br * 128 + row, Nn - 1);
    const __nv_bfloat16* gah = g_Ahi + arow * F0 + k0 + koff;
    const __nv_bfloat16* gal = g_Alo + arow * F0 + k0 + koff;
    size_t nrow = (size_t)(bc * 128 + row);
    const __nv_bfloat16* gbh = g_Bhi + nrow * F0 + k0 + koff;
    const __nv_bfloat16* gbl = g_Blo + nrow * F0 + k0 + koff;
    uint32_t base = smem_u32 + slot * (S_STAGE * 2);
    uint32_t d = base + (row * SROW + koff) * 2;
    cp16(d,                      gah);     cp16(d + 16,                      gah + 8);
    cp16(d + S_A_ELEM * 2,       gal);     cp16(d + S_A_ELEM * 2 + 16,       gal + 8);
    cp16(d + 2 * S_A_ELEM * 2,   gbh);     cp16(d + 2 * S_A_ELEM * 2 + 16,   gbh + 8);
    cp16(d + 3 * S_A_ELEM * 2,   gbl);     cp16(d + 3 * S_A_ELEM * 2 + 16,   gbl + 8);
}

__global__ void __launch_bounds__(256, 1) sgemm_bf16_kernel() {
    extern __shared__ char smem[];
    uint32_t smem_u32 = smem_to_u32(smem);
    int tid = threadIdx.x, lane = tid & 31, wid = tid >> 5;
    int wm = wid & 3, wn = wid >> 2;
    int br = blockIdx.x, bc = blockIdx.y;

    float acc[2][8][4];
#pragma unroll
    for (int i = 0; i < 2; i++)
#pragma unroll
        for (int j = 0; j < 8; j++)
#pragma unroll
            for (int q = 0; q < 4; q++) acc[i][j][q] = 0.f;

    int a_row  = wm * 32 + (lane & 15);
    int a_koff = (lane >> 4) * 8;
    int b_n    = wn * 64 + (lane & 7) + ((lane >> 4) << 3);
    int b_koff = ((lane >> 3) & 1) * 8;

    issue_stage(smem_u32, br, bc, 0, 0);
    CP_COMMIT();
    issue_stage(smem_u32, br, bc, 1, KCHUNK);
    CP_COMMIT();

    for (int i = 0; i < NSTAGE; i++) {
        if (i + 2 < NSTAGE) CP_WAIT(1); else CP_WAIT(0);
        __syncthreads();
        if (i + 2 < NSTAGE) {
            issue_stage(smem_u32, br, bc, (i + 2) % 3, (i + 2) * KCHUNK);
            CP_COMMIT();
        }
        uint32_t stage = smem_u32 + (i % 3) * (S_STAGE * 2);
#pragma unroll
        for (int kk = 0; kk < KCHUNK; kk += 16) {
            uint32_t ahi[2][4], alo[2][4];
#pragma unroll
            for (int t = 0; t < 2; t++) {
                uint32_t addr = stage + ((a_row + t * 16) * SROW + kk + a_koff) * 2;
                LDSM4(ahi[t][0], ahi[t][1], ahi[t][2], ahi[t][3], addr);
                LDSM4(alo[t][0], alo[t][1], alo[t][2], alo[t][3], addr + S_A_ELEM * 2);
            }
            uint32_t bhi[8][2], blo[8][2];
#pragma unroll
            for (int p = 0; p < 4; p++) {
                uint32_t addr = stage + (2 * S_A_ELEM + (b_n + p * 16) * SROW + kk + b_koff) * 2;
                uint32_t r0, r1, r2, r3;
                LDSM4(r0, r1, r2, r3, addr);
                bhi[2 * p][0] = r0; bhi[2 * p][1] = r1;
                bhi[2 * p + 1][0] = r2; bhi[2 * p + 1][1] = r3;
                LDSM4(r0, r1, r2, r3, addr + S_A_ELEM * 2);
                blo[2 * p][0] = r0; blo[2 * p][1] = r1;
                blo[2 * p + 1][0] = r2; blo[2 * p + 1][1] = r3;
            }
#pragma unroll
            for (int mt = 0; mt < 2; mt++)
#pragma unroll
                for (int nt = 0; nt < 8; nt++) {
                    MMA16816(acc[mt][nt], ahi[mt], bhi[nt]);
                    MMA16816(acc[mt][nt], ahi[mt], blo[nt]);
                    MMA16816(acc[mt][nt], alo[mt], bhi[nt]);
                }
        }
        __syncthreads();
    }

#pragma unroll
    for (int mt = 0; mt < 2; mt++) {
        int r0 = br * 128 + wm * 32 + mt * 16 + (lane >> 2);
        int r1 = r0 + 8;
#pragma unroll
        for (int nt = 0; nt < 8; nt++) {
            int col = bc * 128 + wn * 64 + nt * 8 + (lane & 3) * 2;
            if (r0 < Nn)
                *(float2*)(g_xw + (size_t)r0 * NCAT + col) = make_float2(acc[mt][nt][0], acc[mt][nt][1]);
            if (r1 < Nn)
                *(float2*)(g_xw + (size_t)r1 * NCAT + col) = make_float2(acc[mt][nt][2], acc[mt][nt][3]);
        }
    }
}

// ================= CSR build (per tower; reused by both spmm layers) =================
__global__ void zero_deg_kernel() {
    int idx = blockIdx.x * blockDim.x + threadIdx.x;
    if (idx < 2 * Nn) ((int*)g_deg)[idx] = 0;
}

__global__ void hist_kernel(const int* __restrict__ ei1, const int* __restrict__ ei2) {
    int idx = blockIdx.x * blockDim.x + threadIdx.x;
    if (idx >= 2 * EE) return;
    int t = idx >= EE;
    int e = t ? idx - EE : idx;
    const int* ei = t ? ei2 : ei1;
    atomicAdd(&g_deg[t][__ldg(ei + EE + e)], 1);
}

// one block per tower; 1024 threads, each owns a contiguous chunk of rows
__global__ __launch_bounds__(1024) void scan_kernel() {
    int t = blockIdx.x;
    int tid = threadIdx.x, lane = tid & 31, wid = tid >> 5;
    const int CH = (Nn + 1023) / 1024;   // 49
    int base = tid * CH;
    int hi = min(base + CH, Nn);
    int sum = 0;
    for (int i = base; i < hi; i++) sum += g_deg[t][i];
    int x = sum;
#pragma unroll
    for (int o = 1; o < 32; o <<= 1) {
        int y = __shfl_up_sync(0xffffffff, x, o);
        if (lane >= o) x += y;
    }
    __shared__ int wsum[32];
    if (lane == 31) wsum[wid] = x;
    __syncthreads();
    if (wid == 0) {
        int z = wsum[lane];
#pragma unroll
        for (int o = 1; o < 32; o <<= 1) {
            int y = __shfl_up_sync(0xffffffff, z, o);
            if (lane >= o) z += y;
        }
        wsum[lane] = z;
    }
    __syncthreads();
    int incl = x + (wid > 0 ? wsum[wid - 1] : 0);
    int run = incl - sum;
    for (int i = base; i < hi; i++) {
        int d = g_deg[t][i];
        g_off[t][i] = run;
        g_deg[t][i] = run;   // becomes scatter cursor
        run += d;
    }
    if (tid == 1023) g_off[t][Nn] = incl;
}

__global__ void scatter_kernel(const int* __restrict__ ei1, const float* __restrict__ ev1,
                               const int* __restrict__ ei2, const float* __restrict__ ev2) {
    int idx = blockIdx.x * blockDim.x + threadIdx.x;
    if (idx >= 2 * EE) return;
    int t = idx >= EE;
    int e = t ? idx - EE : idx;
    const int* ei = t ? ei2 : ei1;
    const float* ev = t ? ev2 : ev1;
    int src = __ldg(ei + e);
    int dst = __ldg(ei + EE + e);
    int pos = atomicAdd(&g_deg[t][dst], 1);
    g_esrc[t][pos] = src;
    g_eval[t][pos] = __ldg(ev + e);
}

// ---------------- CSR SpMM F=128: h = relu(sum + b); 32 threads/row; 4-edge unroll ----------------
__global__ __launch_bounds__(256) void spmm_csr128_kernel(const float* __restrict__ b1,
                                                          const float* __restrict__ b3) {
    int idx = blockIdx.x * blockDim.x + threadIdx.x;   // Nn * 32
    if (idx >= Nn * 32) return;
    int t = blockIdx.y;
    int row = idx >> 5;
    int c = (idx & 31) * 4;
    int s0 = __ldg(&g_off[t][row]), s1 = __ldg(&g_off[t][row + 1]);
    const int*   es = g_esrc[t];
    const float* evv = g_eval[t];
    const float* feat = g_xw + t * HH + c;
    float ax = 0.f, ay = 0.f, az = 0.f, aw = 0.f;
    int e = s0;
    for (; e + 4 <= s1; e += 4) {
        int   sA = __ldg(es + e),     sB = __ldg(es + e + 1);
        int   sC = __ldg(es + e + 2), sD = __ldg(es + e + 3);
        float vA = __ldg(evv + e),    vB = __ldg(evv + e + 1);
        float vC = __ldg(evv + e + 2), vD = __ldg(evv + e + 3);
        float4 fA = *(const float4*)(feat + (size_t)sA * NCAT);
        float4 fB = *(const float4*)(feat + (size_t)sB * NCAT);
        float4 fC = *(const float4*)(feat + (size_t)sC * NCAT);
        float4 fD = *(const float4*)(feat + (size_t)sD * NCAT);
        ax += vA * fA.x + vB * fB.x + vC * fC.x + vD * fD.x;
        ay += vA * fA.y + vB * fB.y + vC * fC.y + vD * fD.y;
        az += vA * fA.z + vB * fB.z + vC * fC.z + vD * fD.z;
        aw += vA * fA.w + vB * fB.w + vC * fC.w + vD * fD.w;
    }
    for (; e < s1; e++) {
        int   sA = __ldg(es + e);
        float vA = __ldg(evv + e);
        float4 fA = *(const float4*)(feat + (size_t)sA * NCAT);
        ax += vA * fA.x; ay += vA * fA.y; az += vA * fA.z; aw += vA * fA.w;
    }
    const float* b = t ? b3 : b1;
    float4 bv = *(const float4*)(b + c);
    float4 r;
    r.x = fmaxf(ax + bv.x, 0.f);
    r.y = fmaxf(ay + bv.y, 0.f);
    r.z = fmaxf(az + bv.z, 0.f);
    r.w = fmaxf(aw + bv.w, 0.f);
    *(float4*)(g_h[t] + (size_t)row * HH + c) = r;
}

// ---------------- hw = h @ W  (128 -> 40); grid.y = tower ----------------
__global__ __launch_bounds__(240) void gemm2_kernel(const float* __restrict__ W2, const float* __restrict__ W4) {
    __shared__ float sW[HH * CC];   // 20 KB
    int tower = blockIdx.y;
    const float* W = tower ? W4 : W2;
    int tid = threadIdx.y * CC + threadIdx.x;
    for (int i = tid; i < HH * CC; i += 240) sW[i] = W[i];
    __syncthreads();
    int row = blockIdx.x * 6 + threadIdx.y;
    int col = threadIdx.x;
    if (row >= Nn) return;
    const float4* hr = (const float4*)(g_h[tower] + (size_t)row * HH);
    float acc = 0.f;
#pragma unroll
    for (int k4 = 0; k4 < HH / 4; k4++) {
        float4 hv = hr[k4];
        int k = k4 * 4;
        acc += hv.x * sW[(k + 0) * CC + col];
        acc += hv.y * sW[(k + 1) * CC + col];
        acc += hv.z * sW[(k + 2) * CC + col];
        acc += hv.w * sW[(k + 3) * CC + col];
    }
    g_hw[tower][(size_t)row * CC + col] = acc;
}

// ---------------- CSR SpMM F=40: o = sum + b; 10 threads/row ----------------
__global__ __launch_bounds__(250) void spmm_csr40_kernel(const float* __restrict__ b2,
                                                         const float* __restrict__ b4) {
    int idx = blockIdx.x * blockDim.x + threadIdx.x;   // Nn * 10
    if (idx >= Nn * 10) return;
    int t = blockIdx.y;
    int row = idx / 10;
    int c = (idx - row * 10) * 4;
    int s0 = __ldg(&g_off[t][row]), s1 = __ldg(&g_off[t][row + 1]);
    const int*   es = g_esrc[t];
    const float* evv = g_eval[t];
    const float* feat = g_hw[t] + c;
    float ax = 0.f, ay = 0.f, az = 0.f, aw = 0.f;
    int e = s0;
    for (; e + 4 <= s1; e += 4) {
        int   sA = __ldg(es + e),      sB = __ldg(es + e + 1);
        int   sC = __ldg(es + e + 2),  sD = __ldg(es + e + 3);
        float vA = __ldg(evv + e),     vB = __ldg(evv + e + 1);
        float vC = __ldg(evv + e + 2), vD = __ldg(evv + e + 3);
        float4 fA = *(const float4*)(feat + (size_t)sA * CC);
        float4 fB = *(const float4*)(feat + (size_t)sB * CC);
        float4 fC = *(const float4*)(feat + (size_t)sC * CC);
        float4 fD = *(const float4*)(feat + (size_t)sD * CC);
        ax += vA * fA.x + vB * fB.x + vC * fC.x + vD * fD.x;
        ay += vA * fA.y + vB * fB.y + vC * fC.y + vD * fD.y;
        az += vA * fA.z + vB * fB.z + vC * fC.z + vD * fD.z;
        aw += vA * fA.w + vB * fB.w + vC * fC.w + vD * fD.w;
    }
    for (; e < s1; e++) {
        int   sA = __ldg(es + e);
        float vA = __ldg(evv + e);
        float4 fA = *(const float4*)(feat + (size_t)sA * CC);
        ax += vA * fA.x; ay += vA * fA.y; az += vA * fA.z; aw += vA * fA.w;
    }
    const float* b = t ? b4 : b2;
    float* o = g_o[t] + (size_t)row * CC + c;
    o[0] = ax + b[c];
    o[1] = ay + b[c + 1];
    o[2] = az + b[c + 2];
    o[3] = aw + b[c + 3];
}

// ---------------- gated fusion + log_softmax; one warp per row ----------------
__global__ __launch_bounds__(256) void fuse_kernel(const float* __restrict__ Wl,
                                                   const float* __restrict__ bl,
                                                   float* __restrict__ out) {
    __shared__ float sWl[2 * CC * CC];   // 80x40 = 12.8 KB
    __shared__ float sbl[CC];
    __shared__ float scat[8][2 * CC];
    int tid = threadIdx.x;
    for (int i = tid; i < 2 * CC * CC; i += 256) sWl[i] = Wl[i];
    if (tid < CC) sbl[tid] = bl[tid];
    __syncthreads();

    int w = tid >> 5, lane = tid & 31;
    int row = blockIdx.x * 8 + w;
    if (row >= Nn) return;

    const float* o1 = g_o[0] + (size_t)row * CC;
    const float* o2 = g_o[1] + (size_t)row * CC;
    for (int j = lane; j < 2 * CC; j += 32)
        scat[w][j] = (j < CC) ? o1[j] : o2[j - CC];
    __syncwarp();

    float v0, v1 = -INFINITY;
    {
        int c = lane;
        float a = sbl[c];
#pragma unroll
        for (int j = 0; j < 2 * CC; j++) a += scat[w][j] * sWl[j * CC + c];
        float g = 1.f / (1.f + __expf(-a));
        v0 = g * scat[w][c] + (1.f - g) * scat[w][CC + c];
    }
    if (lane < 8) {
        int c = 32 + lane;
        float a = sbl[c];
#pragma unroll
        for (int j = 0; j < 2 * CC; j++) a += scat[w][j] * sWl[j * CC + c];
        float g = 1.f / (1.f + __expf(-a));
        v1 = g * scat[w][c] + (1.f - g) * scat[w][CC + c];
    }
    float m = fmaxf(v0, v1);
#pragma unroll
    for (int o = 16; o > 0; o >>= 1) m = fmaxf(m, __shfl_xor_sync(0xffffffff, m, o));
    float s = expf(v0 - m) + (lane < 8 ? expf(v1 - m) : 0.f);
#pragma unroll
    for (int o = 16; o > 0; o >>= 1) s += __shfl_xor_sync(0xffffffff, s, o);
    float lse = m + logf(s);

    out[(size_t)row * CC + lane] = v0 - lse;
    if (lane < 8) out[(size_t)row * CC + 32 + lane] = v1 - lse;
}

// ---------------- launch ----------------
extern "C" void kernel_launch(void* const* d_in, const int* in_sizes, int n_in,
                              void* d_out, int out_size) {
    const float* x   = (const float*)d_in[0];
    const int*   ei1 = (const int*)  d_in[1];
    const float* ev1 = (const float*)d_in[2];
    const int*   ei2 = (const int*)  d_in[3];
    const float* ev2 = (const float*)d_in[4];
    const float* W1  = (const float*)d_in[5];
    const float* b1  = (const float*)d_in[6];
    const float* W2  = (const float*)d_in[7];
    const float* b2  = (const float*)d_in[8];
    const float* W3  = (const float*)d_in[9];
    const float* b3  = (const float*)d_in[10];
    const float* W4  = (const float*)d_in[11];
    const float* b4  = (const float*)d_in[12];
    const float* Wl  = (const float*)d_in[13];
    const float* bl  = (const float*)d_in[14];
    float* out = (float*)d_out;

    static cudaStream_t s_csr = nullptr;
    static cudaEvent_t ev_fork = nullptr, ev_join = nullptr;
    if (s_csr == nullptr) {
        cudaFuncSetAttribute(sgemm_bf16_kernel, cudaFuncAttributeMaxDynamicSharedMemorySize, S_TOTAL_BYTES);
        cudaStreamCreateWithFlags(&s_csr, cudaStreamNonBlocking);
        cudaEventCreateWithFlags(&ev_fork, cudaEventDisableTiming);
        cudaEventCreateWithFlags(&ev_join, cudaEventDisableTiming);
    }

    // ---- fork: CSR build on side stream, overlapped with dense chain ----
    cudaEventRecord(ev_fork, 0);
    cudaStreamWaitEvent(s_csr, ev_fork, 0);
    zero_deg_kernel<<<(2 * Nn + 255) / 256, 256, 0, s_csr>>>();
    hist_kernel<<<(2 * EE + 255) / 256, 256, 0, s_csr>>>(ei1, ei2);
    scan_kernel<<<2, 1024, 0, s_csr>>>();
    scatter_kernel<<<(2 * EE + 255) / 256, 256, 0, s_csr>>>(ei1, ev1, ei2, ev2);
    cudaEventRecord(ev_join, s_csr);

    // ---- dense chain on main stream ----
    pack_w_kernel<<<(NCAT * F0 + 255) / 256, 256>>>(W1, W3);
    convert_x_kernel<<<(Nn * F0 / 4 + 255) / 256, 256>>>(x);
    {
        dim3 g((Nn + 127) / 128, 2);
        sgemm_bf16_kernel<<<g, 256, S_TOTAL_BYTES>>>();
    }

    // ---- join: spmm needs both CSR and g_xw ----
    cudaStreamWaitEvent(0, ev_join, 0);

    // SpMM layer 1 (CSR, fused bias+relu), both towers
    {
        dim3 g((Nn * 32 + 255) / 256, 2);
        spmm_csr128_kernel<<<g, 256>>>(b1, b3);
    }
    // small GEMMs
    {
        dim3 blk(CC, 6);
        dim3 g((Nn + 5) / 6, 2);
        gemm2_kernel<<<g, blk>>>(W2, W4);
    }
    // SpMM layer 2 (CSR, fused bias), both towers
    {
        dim3 g((Nn * 10 + 249) / 250, 2);
        spmm_csr40_kernel<<<g, 250>>>(b2, b4);
    }
    // gated fusion + log_softmax
    fuse_kernel<<<(Nn + 7) / 8, 256>>>(Wl, bl, out);
}

// round 12
// speedup vs baseline: 4.3176x; 1.1054x over previous
#include <cuda_runtime.h>
#include <cuda_bf16.h>
#include <math.h>
#include <cstdint>

#define Nn     50000
#define F0     512
#define HH     128
#define CC     40
#define EE     800000
#define NCAT   256   // packed output cols: W1 -> 0..127, W3 -> 128..255

// ---------------- scratch (static device globals; no allocation) ----------------
__device__ __nv_bfloat16 g_Ahi[(size_t)Nn * F0];
__device__ __nv_bfloat16 g_Alo[(size_t)Nn * F0];
__device__ __nv_bfloat16 g_Bhi[NCAT * F0];   // [n][k] K-major (transposed Wcat)
__device__ __nv_bfloat16 g_Blo[NCAT * F0];
__device__ float g_xw[(size_t)Nn * NCAT];    // X @ [W1 | W3]
__device__ float g_hw[2][Nn * CC];           // relu(spmm1+b) @ W2/W4
// CSR (dst-binned edges, reused by both spmm layers)
__device__ int   g_deg[2][Nn];               // degree -> cursor (reused)
__device__ int   g_off[2][Nn + 1];
__device__ int   g_esrc[2][EE];
__device__ float g_eval[2][EE];

// ======================= helpers =======================
__device__ __forceinline__ uint32_t smem_to_u32(const void* p) {
    uint32_t a;
    asm("{ .reg .u64 t; cvta.to.shared.u64 t, %1; cvt.u32.u64 %0, t; }" : "=r"(a) : "l"(p));
    return a;
}
__device__ __forceinline__ void cp16(uint32_t dst, const void* src) {
    asm volatile("cp.async.cg.shared.global [%0], [%1], 16;" :: "r"(dst), "l"(src));
}
#define CP_COMMIT() asm volatile("cp.async.commit_group;" ::: "memory")
#define CP_WAIT(n)  asm volatile("cp.async.wait_group %0;" :: "n"(n) : "memory")

#define LDSM4(r0, r1, r2, r3, addr) \
    asm volatile("ldmatrix.sync.aligned.m8n8.x4.shared.b16 {%0,%1,%2,%3}, [%4];" \
                 : "=r"(r0), "=r"(r1), "=r"(r2), "=r"(r3) : "r"(addr))

#define MMA16816(d, a, b) \
    asm volatile("mma.sync.aligned.m16n8k16.row.col.f32.bf16.bf16.f32 " \
                 "{%0,%1,%2,%3}, {%4,%5,%6,%7}, {%8,%9}, {%0,%1,%2,%3};" \
                 : "+f"((d)[0]), "+f"((d)[1]), "+f"((d)[2]), "+f"((d)[3]) \
                 : "r"((a)[0]), "r"((a)[1]), "r"((a)[2]), "r"((a)[3]), \
                   "r"((b)[0]), "r"((b)[1]))

// ---------------- pack W1,W3 transposed into bf16 hi/lo [NCAT][F0] ----------------
__global__ void pack_w_kernel(const float* __restrict__ W1, const float* __restrict__ W3) {
    int idx = blockIdx.x * blockDim.x + threadIdx.x;   // NCAT * F0, k fastest
    if (idx >= NCAT * F0) return;
    int n = idx >> 9, k = idx & (F0 - 1);
    float w = (n < HH) ? W1[k * HH + n] : W3[k * HH + (n - HH)];
    __nv_bfloat16 hi = __float2bfloat16_rn(w);
    g_Bhi[idx] = hi;
    g_Blo[idx] = __float2bfloat16_rn(w - __bfloat162float(hi));
}

// ---------------- convert X fp32 -> bf16 hi/lo ----------------
__global__ void convert_x_kernel(const float* __restrict__ x) {
    int idx = blockIdx.x * blockDim.x + threadIdx.x;   // Nn*F0/4 float4s
    if (idx >= Nn * F0 / 4) return;
    float4 v = ((const float4*)x)[idx];
    __nv_bfloat16 h0 = __float2bfloat16_rn(v.x), h1 = __float2bfloat16_rn(v.y);
    __nv_bfloat16 h2 = __float2bfloat16_rn(v.z), h3 = __float2bfloat16_rn(v.w);
    __nv_bfloat16 l0 = __float2bfloat16_rn(v.x - __bfloat162float(h0));
    __nv_bfloat16 l1 = __float2bfloat16_rn(v.y - __bfloat162float(h1));
    __nv_bfloat16 l2 = __float2bfloat16_rn(v.z - __bfloat162float(h2));
    __nv_bfloat16 l3 = __float2bfloat16_rn(v.w - __bfloat162float(h3));
    __nv_bfloat162 hp0 = __halves2bfloat162(h0, h1), hp1 = __halves2bfloat162(h2, h3);
    __nv_bfloat162 lp0 = __halves2bfloat162(l0, l1), lp1 = __halves2bfloat162(l2, l3);
    uint2 hu, lu;
    hu.x = *(uint32_t*)&hp0; hu.y = *(uint32_t*)&hp1;
    lu.x = *(uint32_t*)&lp0; lu.y = *(uint32_t*)&lp1;
    ((uint2*)g_Ahi)[idx] = hu;
    ((uint2*)g_Alo)[idx] = lu;
}

// ---------------- bf16 split GEMM via mma.sync ----------------
#define SROW     40
#define S_A_ELEM (128 * SROW)
#define S_STAGE  (4 * S_A_ELEM)
#define S_TOTAL_BYTES (3 * S_STAGE * 2)
#define KCHUNK   32
#define NSTAGE   (F0 / KCHUNK)

__device__ __forceinline__ void issue_stage(uint32_t smem_u32, int br, int bc, int slot, int k0) {
    int t = threadIdx.x;
    int row = t >> 1, half = t & 1;
    int koff = half * 16;
    size_t arow = (size_t)min(br * 128 + row, Nn - 1);
    const __nv_bfloat16* gah = g_Ahi + arow * F0 + k0 + koff;
    const __nv_bfloat16* gal = g_Alo + arow * F0 + k0 + koff;
    size_t nrow = (size_t)(bc * 128 + row);
    const __nv_bfloat16* gbh = g_Bhi + nrow * F0 + k0 + koff;
    const __nv_bfloat16* gbl = g_Blo + nrow * F0 + k0 + koff;
    uint32_t base = smem_u32 + slot * (S_STAGE * 2);
    uint32_t d = base + (row * SROW + koff) * 2;
    cp16(d,                      gah);     cp16(d + 16,                      gah + 8);
    cp16(d + S_A_ELEM * 2,       gal);     cp16(d + S_A_ELEM * 2 + 16,       gal + 8);
    cp16(d + 2 * S_A_ELEM * 2,   gbh);     cp16(d + 2 * S_A_ELEM * 2 + 16,   gbh + 8);
    cp16(d + 3 * S_A_ELEM * 2,   gbl);     cp16(d + 3 * S_A_ELEM * 2 + 16,   gbl + 8);
}

// grid (2, 391): bc = x (fast) so the two CTAs sharing an A row-block co-schedule -> A L2 reuse
__global__ void __launch_bounds__(256, 1) sgemm_bf16_kernel() {
    extern __shared__ char smem[];
    uint32_t smem_u32 = smem_to_u32(smem);
    int tid = threadIdx.x, lane = tid & 31, wid = tid >> 5;
    int wm = wid & 3, wn = wid >> 2;
    int bc = blockIdx.x, br = blockIdx.y;

    float acc[2][8][4];
#pragma unroll
    for (int i = 0; i < 2; i++)
#pragma unroll
        for (int j = 0; j < 8; j++)
#pragma unroll
            for (int q = 0; q < 4; q++) acc[i][j][q] = 0.f;

    int a_row  = wm * 32 + (lane & 15);
    int a_koff = (lane >> 4) * 8;
    int b_n    = wn * 64 + (lane & 7) + ((lane >> 4) << 3);
    int b_koff = ((lane >> 3) & 1) * 8;

    issue_stage(smem_u32, br, bc, 0, 0);
    CP_COMMIT();
    issue_stage(smem_u32, br, bc, 1, KCHUNK);
    CP_COMMIT();

    for (int i = 0; i < NSTAGE; i++) {
        if (i + 2 < NSTAGE) CP_WAIT(1); else CP_WAIT(0);
        __syncthreads();
        if (i + 2 < NSTAGE) {
            issue_stage(smem_u32, br, bc, (i + 2) % 3, (i + 2) * KCHUNK);
            CP_COMMIT();
        }
        uint32_t stage = smem_u32 + (i % 3) * (S_STAGE * 2);
#pragma unroll
        for (int kk = 0; kk < KCHUNK; kk += 16) {
            uint32_t ahi[2][4], alo[2][4];
#pragma unroll
            for (int t = 0; t < 2; t++) {
                uint32_t addr = stage + ((a_row + t * 16) * SROW + kk + a_koff) * 2;
                LDSM4(ahi[t][0], ahi[t][1], ahi[t][2], ahi[t][3], addr);
                LDSM4(alo[t][0], alo[t][1], alo[t][2], alo[t][3], addr + S_A_ELEM * 2);
            }
            uint32_t bhi[8][2], blo[8][2];
#pragma unroll
            for (int p = 0; p < 4; p++) {
                uint32_t addr = stage + (2 * S_A_ELEM + (b_n + p * 16) * SROW + kk + b_koff) * 2;
                uint32_t r0, r1, r2, r3;
                LDSM4(r0, r1, r2, r3, addr);
                bhi[2 * p][0] = r0; bhi[2 * p][1] = r1;
                bhi[2 * p + 1][0] = r2; bhi[2 * p + 1][1] = r3;
                LDSM4(r0, r1, r2, r3, addr + S_A_ELEM * 2);
                blo[2 * p][0] = r0; blo[2 * p][1] = r1;
                blo[2 * p + 1][0] = r2; blo[2 * p + 1][1] = r3;
            }
#pragma unroll
            for (int mt = 0; mt < 2; mt++)
#pragma unroll
                for (int nt = 0; nt < 8; nt++) {
                    MMA16816(acc[mt][nt], ahi[mt], bhi[nt]);
                    MMA16816(acc[mt][nt], ahi[mt], blo[nt]);
                    MMA16816(acc[mt][nt], alo[mt], bhi[nt]);
                }
        }
        __syncthreads();
    }

#pragma unroll
    for (int mt = 0; mt < 2; mt++) {
        int r0 = br * 128 + wm * 32 + mt * 16 + (lane >> 2);
        int r1 = r0 + 8;
#pragma unroll
        for (int nt = 0; nt < 8; nt++) {
            int col = bc * 128 + wn * 64 + nt * 8 + (lane & 3) * 2;
            if (r0 < Nn)
                *(float2*)(g_xw + (size_t)r0 * NCAT + col) = make_float2(acc[mt][nt][0], acc[mt][nt][1]);
            if (r1 < Nn)
                *(float2*)(g_xw + (size_t)r1 * NCAT + col) = make_float2(acc[mt][nt][2], acc[mt][nt][3]);
        }
    }
}

// ================= CSR build (per tower; reused by both spmm layers) =================
__global__ void zero_deg_kernel() {
    int idx = blockIdx.x * blockDim.x + threadIdx.x;
    if (idx < 2 * Nn) ((int*)g_deg)[idx] = 0;
}

__global__ void hist_kernel(const int* __restrict__ ei1, const int* __restrict__ ei2) {
    int idx = blockIdx.x * blockDim.x + threadIdx.x;
    if (idx >= 2 * EE) return;
    int t = idx >= EE;
    int e = t ? idx - EE : idx;
    const int* ei = t ? ei2 : ei1;
    atomicAdd(&g_deg[t][__ldg(ei + EE + e)], 1);
}

__global__ __launch_bounds__(1024) void scan_kernel() {
    int t = blockIdx.x;
    int tid = threadIdx.x, lane = tid & 31, wid = tid >> 5;
    const int CH = (Nn + 1023) / 1024;   // 49
    int base = tid * CH;
    int hi = min(base + CH, Nn);
    int sum = 0;
    for (int i = base; i < hi; i++) sum += g_deg[t][i];
    int x = sum;
#pragma unroll
    for (int o = 1; o < 32; o <<= 1) {
        int y = __shfl_up_sync(0xffffffff, x, o);
        if (lane >= o) x += y;
    }
    __shared__ int wsum[32];
    if (lane == 31) wsum[wid] = x;
    __syncthreads();
    if (wid == 0) {
        int z = wsum[lane];
#pragma unroll
        for (int o = 1; o < 32; o <<= 1) {
            int y = __shfl_up_sync(0xffffffff, z, o);
            if (lane >= o) z += y;
        }
        wsum[lane] = z;
    }
    __syncthreads();
    int incl = x + (wid > 0 ? wsum[wid - 1] : 0);
    int run = incl - sum;
    for (int i = base; i < hi; i++) {
        int d = g_deg[t][i];
        g_off[t][i] = run;
        g_deg[t][i] = run;   // becomes scatter cursor
        run += d;
    }
    if (tid == 1023) g_off[t][Nn] = incl;
}

__global__ void scatter_kernel(const int* __restrict__ ei1, const float* __restrict__ ev1,
                               const int* __restrict__ ei2, const float* __restrict__ ev2) {
    int idx = blockIdx.x * blockDim.x + threadIdx.x;
    if (idx >= 2 * EE) return;
    int t = idx >= EE;
    int e = t ? idx - EE : idx;
    const int* ei = t ? ei2 : ei1;
    const float* ev = t ? ev2 : ev1;
    int src = __ldg(ei + e);
    int dst = __ldg(ei + EE + e);
    int pos = atomicAdd(&g_deg[t][dst], 1);
    g_esrc[t][pos] = src;
    g_eval[t][pos] = __ldg(ev + e);
}

// ====== fused: spmm1(F=128) + bias + relu + (h @ W2/W4) -> g_hw; 32 rows/block ======
#define SP1_ROWS 32
#define SHPAD    132   // 128 + 4 pad: r vs r+1 in different banks for phase-2 broadcast
__global__ __launch_bounds__(256) void spmm128_gemm2_kernel(const float* __restrict__ b1,
                                                            const float* __restrict__ b3,
                                                            const float* __restrict__ W2,
                                                            const float* __restrict__ W4) {
    __shared__ float sh[SP1_ROWS][SHPAD];   // 16.9 KB
    __shared__ float sW[HH * CC];           // 20 KB
    int t = blockIdx.y;
    const float* W = t ? W4 : W2;
    const float* b = t ? b3 : b1;
    int tid = threadIdx.x;
    for (int i = tid; i < HH * CC; i += 256) sW[i] = W[i];

    int g = tid >> 5, lane = tid & 31;
    int c = lane * 4;
    float4 bv = *(const float4*)(b + c);
    int row0 = blockIdx.x * SP1_ROWS;
    const int*   es  = g_esrc[t];
    const float* evv = g_eval[t];
    const float* feat = g_xw + t * HH + c;

#pragma unroll
    for (int rr = g; rr < SP1_ROWS; rr += 8) {
        int row = row0 + rr;
        if (row >= Nn) break;
        int s0 = __ldg(&g_off[t][row]), s1 = __ldg(&g_off[t][row + 1]);
        float ax = 0.f, ay = 0.f, az = 0.f, aw = 0.f;
        int e = s0;
        for (; e + 4 <= s1; e += 4) {
            int   sA = __ldg(es + e),      sB = __ldg(es + e + 1);
            int   sC = __ldg(es + e + 2),  sD = __ldg(es + e + 3);
            float vA = __ldg(evv + e),     vB = __ldg(evv + e + 1);
            float vC = __ldg(evv + e + 2), vD = __ldg(evv + e + 3);
            float4 fA = *(const float4*)(feat + (size_t)sA * NCAT);
            float4 fB = *(const float4*)(feat + (size_t)sB * NCAT);
            float4 fC = *(const float4*)(feat + (size_t)sC * NCAT);
            float4 fD = *(const float4*)(feat + (size_t)sD * NCAT);
            ax += vA * fA.x + vB * fB.x + vC * fC.x + vD * fD.x;
            ay += vA * fA.y + vB * fB.y + vC * fC.y + vD * fD.y;
            az += vA * fA.z + vB * fB.z + vC * fC.z + vD * fD.z;
            aw += vA * fA.w + vB * fB.w + vC * fC.w + vD * fD.w;
        }
        for (; e < s1; e++) {
            int   sA = __ldg(es + e);
            float vA = __ldg(evv + e);
            float4 fA = *(const float4*)(feat + (size_t)sA * NCAT);
            ax += vA * fA.x; ay += vA * fA.y; az += vA * fA.z; aw += vA * fA.w;
        }
        sh[rr][c + 0] = fmaxf(ax + bv.x, 0.f);
        sh[rr][c + 1] = fmaxf(ay + bv.y, 0.f);
        sh[rr][c + 2] = fmaxf(az + bv.z, 0.f);
        sh[rr][c + 3] = fmaxf(aw + bv.w, 0.f);
    }
    __syncthreads();

    // phase 2: hw[r][cc] = sum_k sh[r][k] * sW[k*CC+cc]
#pragma unroll
    for (int oi = tid; oi < SP1_ROWS * CC; oi += 256) {
        int r = oi / CC, cc = oi - r * CC;
        int row = row0 + r;
        if (row >= Nn) continue;
        float acc = 0.f;
        const float4* shr = (const float4*)&sh[r][0];
#pragma unroll
        for (int k4 = 0; k4 < HH / 4; k4++) {
            float4 h = shr[k4];
            int k = k4 * 4;
            acc += h.x * sW[(k + 0) * CC + cc];
            acc += h.y * sW[(k + 1) * CC + cc];
            acc += h.z * sW[(k + 2) * CC + cc];
            acc += h.w * sW[(k + 3) * CC + cc];
        }
        g_hw[t][(size_t)row * CC + cc] = acc;
    }
}

// ====== fused: spmm2(F=40, both towers) + bias + gate + log_softmax -> out; 16 rows/block ======
#define SP2_ROWS 16
__global__ __launch_bounds__(320) void spmm40_fuse_kernel(const float* __restrict__ b2,
                                                          const float* __restrict__ b4,
                                                          const float* __restrict__ Wl,
                                                          const float* __restrict__ bl,
                                                          float* __restrict__ out) {
    __shared__ float sWl[2 * CC * CC];      // 12.8 KB
    __shared__ float sbl[CC];
    __shared__ float so[SP2_ROWS][2 * CC];  // [o1 | o2] per row
    int tid = threadIdx.x;
    for (int i = tid; i < 2 * CC * CC; i += 320) sWl[i] = Wl[i];
    if (tid < CC) sbl[tid] = bl[tid];

    // phase 1: gather; 20 threads per row (10 per tower)
    int rl = tid / 20, sub = tid - rl * 20;
    int t = sub / 10, c = (sub - t * 10) * 4;
    int row = blockIdx.x * SP2_ROWS + rl;
    if (row < Nn) {
        int s0 = __ldg(&g_off[t][row]), s1 = __ldg(&g_off[t][row + 1]);
        const int*   es  = g_esrc[t];
        const float* evv = g_eval[t];
        const float* feat = g_hw[t] + c;
        float ax = 0.f, ay = 0.f, az = 0.f, aw = 0.f;
        int e = s0;
        for (; e + 4 <= s1; e += 4) {
            int   sA = __ldg(es + e),      sB = __ldg(es + e + 1);
            int   sC = __ldg(es + e + 2),  sD = __ldg(es + e + 3);
            float vA = __ldg(evv + e),     vB = __ldg(evv + e + 1);
            float vC = __ldg(evv + e + 2), vD = __ldg(evv + e + 3);
            float4 fA = *(const float4*)(feat + (size_t)sA * CC);
            float4 fB = *(const float4*)(feat + (size_t)sB * CC);
            float4 fC = *(const float4*)(feat + (size_t)sC * CC);
            float4 fD = *(const float4*)(feat + (size_t)sD * CC);
            ax += vA * fA.x + vB * fB.x + vC * fC.x + vD * fD.x;
            ay += vA * fA.y + vB * fB.y + vC * fC.y + vD * fD.y;
            az += vA * fA.z + vB * fB.z + vC * fC.z + vD * fD.z;
            aw += vA * fA.w + vB * fB.w + vC * fC.w + vD * fD.w;
        }
        for (; e < s1; e++) {
            int   sA = __ldg(es + e);
            float vA = __ldg(evv + e);
            float4 fA = *(const float4*)(feat + (size_t)sA * CC);
            ax += vA * fA.x; ay += vA * fA.y; az += vA * fA.z; aw += vA * fA.w;
        }
        const float* b = t ? b4 : b2;
        float4 r4;
        r4.x = ax + b[c];   r4.y = ay + b[c + 1];
        r4.z = az + b[c + 2]; r4.w = aw + b[c + 3];
        *(float4*)&so[rl][t * CC + c] = r4;
    }
    __syncthreads();

    // phase 2: gate + log_softmax; warps 0..7, each handles rows 2w, 2w+1
    int w = tid >> 5, lane = tid & 31;
    if (w < 8) {
#pragma unroll
        for (int rp = 0; rp < 2; rp++) {
            int rl2 = w * 2 + rp;
            int row2 = blockIdx.x * SP2_ROWS + rl2;
            if (row2 >= Nn) continue;
            const float* sr = so[rl2];
            float v0, v1 = -INFINITY;
            {
                int cc = lane;
                float a = sbl[cc];
#pragma unroll
                for (int j = 0; j < 2 * CC; j++) a += sr[j] * sWl[j * CC + cc];
                float gg = 1.f / (1.f + __expf(-a));
                v0 = gg * sr[cc] + (1.f - gg) * sr[CC + cc];
            }
            if (lane < 8) {
                int cc = 32 + lane;
                float a = sbl[cc];
#pragma unroll
                for (int j = 0; j < 2 * CC; j++) a += sr[j] * sWl[j * CC + cc];
                float gg = 1.f / (1.f + __expf(-a));
                v1 = gg * sr[cc] + (1.f - gg) * sr[CC + cc];
            }
            float m = fmaxf(v0, v1);
#pragma unroll
            for (int o = 16; o > 0; o >>= 1) m = fmaxf(m, __shfl_xor_sync(0xffffffff, m, o));
            float s = expf(v0 - m) + (lane < 8 ? expf(v1 - m) : 0.f);
#pragma unroll
            for (int o = 16; o > 0; o >>= 1) s += __shfl_xor_sync(0xffffffff, s, o);
            float lse = m + logf(s);
            out[(size_t)row2 * CC + lane] = v0 - lse;
            if (lane < 8) out[(size_t)row2 * CC + 32 + lane] = v1 - lse;
        }
    }
}

// ---------------- launch ----------------
extern "C" void kernel_launch(void* const* d_in, const int* in_sizes, int n_in,
                              void* d_out, int out_size) {
    const float* x   = (const float*)d_in[0];
    const int*   ei1 = (const int*)  d_in[1];
    const float* ev1 = (const float*)d_in[2];
    const int*   ei2 = (const int*)  d_in[3];
    const float* ev2 = (const float*)d_in[4];
    const float* W1  = (const float*)d_in[5];
    const float* b1  = (const float*)d_in[6];
    const float* W2  = (const float*)d_in[7];
    const float* b2  = (const float*)d_in[8];
    const float* W3  = (const float*)d_in[9];
    const float* b3  = (const float*)d_in[10];
    const float* W4  = (const float*)d_in[11];
    const float* b4  = (const float*)d_in[12];
    const float* Wl  = (const float*)d_in[13];
    const float* bl  = (const float*)d_in[14];
    float* out = (float*)d_out;

    static cudaStream_t s_csr = nullptr;
    static cudaEvent_t ev_fork = nullptr, ev_join = nullptr;
    if (s_csr == nullptr) {
        cudaFuncSetAttribute(sgemm_bf16_kernel, cudaFuncAttributeMaxDynamicSharedMemorySize, S_TOTAL_BYTES);
        cudaStreamCreateWithFlags(&s_csr, cudaStreamNonBlocking);
        cudaEventCreateWithFlags(&ev_fork, cudaEventDisableTiming);
        cudaEventCreateWithFlags(&ev_join, cudaEventDisableTiming);
    }

    // ---- fork: CSR build on side stream, overlapped with dense chain ----
    cudaEventRecord(ev_fork, 0);
    cudaStreamWaitEvent(s_csr, ev_fork, 0);
    zero_deg_kernel<<<(2 * Nn + 255) / 256, 256, 0, s_csr>>>();
    hist_kernel<<<(2 * EE + 255) / 256, 256, 0, s_csr>>>(ei1, ei2);
    scan_kernel<<<2, 1024, 0, s_csr>>>();
    scatter_kernel<<<(2 * EE + 255) / 256, 256, 0, s_csr>>>(ei1, ev1, ei2, ev2);
    cudaEventRecord(ev_join, s_csr);

    // ---- dense chain on main stream ----
    pack_w_kernel<<<(NCAT * F0 + 255) / 256, 256>>>(W1, W3);
    convert_x_kernel<<<(Nn * F0 / 4 + 255) / 256, 256>>>(x);
    {
        dim3 g(2, (Nn + 127) / 128);   // bc fast -> A-tile L2 reuse between the pair
        sgemm_bf16_kernel<<<g, 256, S_TOTAL_BYTES>>>();
    }

    // ---- join: spmm needs both CSR and g_xw ----
    cudaStreamWaitEvent(0, ev_join, 0);

    // fused spmm1 + bias + relu + gemm2, both towers
    {
        dim3 g((Nn + SP1_ROWS - 1) / SP1_ROWS, 2);
        spmm128_gemm2_kernel<<<g, 256>>>(b1, b3, W2, W4);
    }
    // fused spmm2 + bias + gate + log_softmax (both towers in one kernel)
    {
        dim3 g((Nn + SP2_ROWS - 1) / SP2_ROWS);
        spmm40_fuse_kernel<<<g, 320>>>(b2, b4, Wl, bl, out);
    }
}

// round 15
// speedup vs baseline: 4.4349x; 1.0272x over previous
#include <cuda_runtime.h>
#include <cuda_bf16.h>
#include <math.h>
#include <cstdint>

#define Nn     50000
#define F0     512
#define HH     128
#define CC     40
#define EE     800000
#define NCAT   256   // packed output cols: W1 -> 0..127, W3 -> 128..255

// ---------------- scratch (static device globals; no allocation) ----------------
__device__ __nv_bfloat16 g_Bhi[NCAT * F0];   // [n][k] K-major (transposed Wcat)
__device__ __nv_bfloat16 g_Blo[NCAT * F0];
__device__ float g_xw[(size_t)Nn * NCAT];    // X @ [W1 | W3]
__device__ float g_hw[2][Nn * CC];           // relu(spmm1+b) @ W2/W4
// CSR (dst-binned edges, reused by both spmm layers)
__device__ int   g_deg[2][Nn];               // degree -> cursor (reused)
__device__ int   g_off[2][Nn + 1];
__device__ int   g_esrc[2][EE];
__device__ float g_eval[2][EE];

// ======================= helpers =======================
__device__ __forceinline__ uint32_t smem_to_u32(const void* p) {
    uint32_t a;
    asm("{ .reg .u64 t; cvta.to.shared.u64 t, %1; cvt.u32.u64 %0, t; }" : "=r"(a) : "l"(p));
    return a;
}
__device__ __forceinline__ void cp16(uint32_t dst, const void* src) {
    asm volatile("cp.async.cg.shared.global [%0], [%1], 16;" :: "r"(dst), "l"(src));
}
#define CP_COMMIT() asm volatile("cp.async.commit_group;" ::: "memory")
#define CP_WAIT(n)  asm volatile("cp.async.wait_group %0;" :: "n"(n) : "memory")

#define LDSM4(r0, r1, r2, r3, addr) \
    asm volatile("ldmatrix.sync.aligned.m8n8.x4.shared.b16 {%0,%1,%2,%3}, [%4];" \
                 : "=r"(r0), "=r"(r1), "=r"(r2), "=r"(r3) : "r"(addr))

#define MMA16816(d, a, b) \
    asm volatile("mma.sync.aligned.m16n8k16.row.col.f32.bf16.bf16.f32 " \
                 "{%0,%1,%2,%3}, {%4,%5,%6,%7}, {%8,%9}, {%0,%1,%2,%3};" \
                 : "+f"((d)[0]), "+f"((d)[1]), "+f"((d)[2]), "+f"((d)[3]) \
                 : "r"((a)[0]), "r"((a)[1]), "r"((a)[2]), "r"((a)[3]), \
                   "r"((b)[0]), "r"((b)[1]))

// ---------------- pack W1,W3 transposed into bf16 hi/lo [NCAT][F0] ----------------
__global__ void pack_w_kernel(const float* __restrict__ W1, const float* __restrict__ W3) {
    int idx = blockIdx.x * blockDim.x + threadIdx.x;   // NCAT * F0, k fastest
    if (idx >= NCAT * F0) return;
    int n = idx >> 9, k = idx & (F0 - 1);
    float w = (n < HH) ? W1[k * HH + n] : W3[k * HH + (n - HH)];
    __nv_bfloat16 hi = __float2bfloat16_rn(w);
    g_Bhi[idx] = hi;
    g_Blo[idx] = __float2bfloat16_rn(w - __bfloat162float(hi));
}

// ---------------- bf16 split GEMM via mma.sync, fp32 A converted in-kernel ----------------
// CTA 128M x 128N; 8 warps (4M x 2N); K chunks of 32; 3-stage cp.async (fp32 A + bf16 B),
// 2-deep converted-A staging buffer. Padded SROW=40 bf16 rows for conflict-free ldmatrix.
#define SROW      40
#define KCHUNK    32
#define NSTAGE    (F0 / KCHUNK)            // 16
#define A32_STAGE (128 * KCHUNK * 4)       // 16384 B (fp32 A tile)
#define B_MAT     (128 * SROW * 2)         // 10240 B (one bf16 matrix, padded)
#define B_STAGE   (2 * B_MAT)              // 20480 B (Bhi | Blo)
#define SM_A32    0                        // 3 stages: 49152
#define SM_B      (3 * A32_STAGE)          // 3 stages: 61440
#define AH_MAT    B_MAT
#define AH_BUF    (2 * AH_MAT)             // Ahi | Alo = 20480
#define SM_AH     (SM_B + 3 * B_STAGE)     // 2 bufs: 40960
#define S_TOTAL_BYTES (SM_AH + 2 * AH_BUF) // 151552

__device__ __forceinline__ void issue_stage(uint32_t smem_u32, const float* __restrict__ x,
                                            int br, int bc, int slot, int k0) {
    int t = threadIdx.x;
    int row = t >> 1, half = t & 1;
    int koff = half * 16;   // elements
    size_t arow = (size_t)min(br * 128 + row, Nn - 1);
    const float* gx = x + arow * F0 + k0 + koff;
    uint32_t da = smem_u32 + SM_A32 + slot * A32_STAGE + (row * KCHUNK + koff) * 4;
    cp16(da, gx); cp16(da + 16, gx + 4); cp16(da + 32, gx + 8); cp16(da + 48, gx + 12);
    size_t nrow = (size_t)(bc * 128 + row);
    const __nv_bfloat16* gbh = g_Bhi + nrow * F0 + k0 + koff;
    const __nv_bfloat16* gbl = g_Blo + nrow * F0 + k0 + koff;
    uint32_t db = smem_u32 + SM_B + slot * B_STAGE + (row * SROW + koff) * 2;
    cp16(db, gbh); cp16(db + 16, gbh + 8);
    cp16(db + B_MAT, gbl); cp16(db + B_MAT + 16, gbl + 8);
}

// grid (2, 391): bc = x (fast) so the two CTAs sharing an A row-block co-schedule -> A L2 reuse
__global__ void __launch_bounds__(256, 1) sgemm_bf16_kernel(const float* __restrict__ x) {
    extern __shared__ char smem[];
    uint32_t smem_u32 = smem_to_u32(smem);
    int tid = threadIdx.x, lane = tid & 31, wid = tid >> 5;
    int wm = wid & 3, wn = wid >> 2;
    int bc = blockIdx.x, br = blockIdx.y;

    float acc[2][8][4];
#pragma unroll
    for (int i = 0; i < 2; i++)
#pragma unroll
        for (int j = 0; j < 8; j++)
#pragma unroll
            for (int q = 0; q < 4; q++) acc[i][j][q] = 0.f;

    int a_row  = wm * 32 + (lane & 15);
    int a_koff = (lane >> 4) * 8;
    int b_n    = wn * 64 + (lane & 7) + ((lane >> 4) << 3);
    int b_koff = ((lane >> 3) & 1) * 8;

    int cv_row = tid >> 1, cv_half = tid & 1;
    int cv_koff = cv_half * 16;

    issue_stage(smem_u32, x, br, bc, 0, 0);
    CP_COMMIT();
    issue_stage(smem_u32, x, br, bc, 1, KCHUNK);
    CP_COMMIT();

    for (int i = 0; i < NSTAGE; i++) {
        int s3 = i % 3, b2 = i & 1;
        if (i + 2 < NSTAGE) CP_WAIT(1); else CP_WAIT(0);
        __syncthreads();
        if (i + 2 < NSTAGE) {
            issue_stage(smem_u32, x, br, bc, (i + 2) % 3, (i + 2) * KCHUNK);
            CP_COMMIT();
        }
        // convert own fp32 A chunk -> bf16 hi/lo staging buffer
        {
            const float* src = (const float*)(smem + SM_A32 + s3 * A32_STAGE) + cv_row * KCHUNK + cv_koff;
            uint32_t hi8[8], lo8[8];
#pragma unroll
            for (int j = 0; j < 4; j++) {
                float4 v = ((const float4*)src)[j];
                __nv_bfloat16 hx = __float2bfloat16_rn(v.x);
                __nv_bfloat16 hy = __float2bfloat16_rn(v.y);
                __nv_bfloat16 hz = __float2bfloat16_rn(v.z);
                __nv_bfloat16 hw = __float2bfloat16_rn(v.w);
                __nv_bfloat162 ph0 = __halves2bfloat162(hx, hy);
                __nv_bfloat162 ph1 = __halves2bfloat162(hz, hw);
                __nv_bfloat162 pl0 = __halves2bfloat162(
                    __float2bfloat16_rn(v.x - __bfloat162float(hx)),
                    __float2bfloat16_rn(v.y - __bfloat162float(hy)));
                __nv_bfloat162 pl1 = __halves2bfloat162(
                    __float2bfloat16_rn(v.z - __bfloat162float(hz)),
                    __float2bfloat16_rn(v.w - __bfloat162float(hw)));
                hi8[2 * j]     = *(uint32_t*)&ph0;
                hi8[2 * j + 1] = *(uint32_t*)&ph1;
                lo8[2 * j]     = *(uint32_t*)&pl0;
                lo8[2 * j + 1] = *(uint32_t*)&pl1;
            }
            char* dsthi = smem + SM_AH + b2 * AH_BUF + (cv_row * SROW + cv_koff) * 2;
            ((uint4*)dsthi)[0] = make_uint4(hi8[0], hi8[1], hi8[2], hi8[3]);
            ((uint4*)dsthi)[1] = make_uint4(hi8[4], hi8[5], hi8[6], hi8[7]);
            char* dstlo = dsthi + AH_MAT;
            ((uint4*)dstlo)[0] = make_uint4(lo8[0], lo8[1], lo8[2], lo8[3]);
            ((uint4*)dstlo)[1] = make_uint4(lo8[4], lo8[5], lo8[6], lo8[7]);
        }
        __syncthreads();

        uint32_t abase = smem_u32 + SM_AH + b2 * AH_BUF;
        uint32_t bbase = smem_u32 + SM_B + s3 * B_STAGE;
#pragma unroll
        for (int kk = 0; kk < KCHUNK; kk += 16) {
            uint32_t ahi[2][4], alo[2][4];
#pragma unroll
            for (int t = 0; t < 2; t++) {
                uint32_t addr = abase + ((a_row + t * 16) * SROW + kk + a_koff) * 2;
                LDSM4(ahi[t][0], ahi[t][1], ahi[t][2], ahi[t][3], addr);
                LDSM4(alo[t][0], alo[t][1], alo[t][2], alo[t][3], addr + AH_MAT);
            }
            uint32_t bhi[8][2], blo[8][2];
#pragma unroll
            for (int p = 0; p < 4; p++) {
                uint32_t addr = bbase + ((b_n + p * 16) * SROW + kk + b_koff) * 2;
                uint32_t r0, r1, r2, r3;
                LDSM4(r0, r1, r2, r3, addr);
                bhi[2 * p][0] = r0; bhi[2 * p][1] = r1;
                bhi[2 * p + 1][0] = r2; bhi[2 * p + 1][1] = r3;
                LDSM4(r0, r1, r2, r3, addr + B_MAT);
                blo[2 * p][0] = r0; blo[2 * p][1] = r1;
                blo[2 * p + 1][0] = r2; blo[2 * p + 1][1] = r3;
            }
#pragma unroll
            for (int mt = 0; mt < 2; mt++)
#pragma unroll
                for (int nt = 0; nt < 8; nt++) {
                    MMA16816(acc[mt][nt], ahi[mt], bhi[nt]);
                    MMA16816(acc[mt][nt], ahi[mt], blo[nt]);
                    MMA16816(acc[mt][nt], alo[mt], bhi[nt]);
                }
        }
    }

#pragma unroll
    for (int mt = 0; mt < 2; mt++) {
        int r0 = br * 128 + wm * 32 + mt * 16 + (lane >> 2);
        int r1 = r0 + 8;
#pragma unroll
        for (int nt = 0; nt < 8; nt++) {
            int col = bc * 128 + wn * 64 + nt * 8 + (lane & 3) * 2;
            if (r0 < Nn)
                *(float2*)(g_xw + (size_t)r0 * NCAT + col) = make_float2(acc[mt][nt][0], acc[mt][nt][1]);
            if (r1 < Nn)
                *(float2*)(g_xw + (size_t)r1 * NCAT + col) = make_float2(acc[mt][nt][2], acc[mt][nt][3]);
        }
    }
}

// ================= CSR build (per tower; reused by both spmm layers) =================
__global__ void zero_deg_kernel() {
    int idx = blockIdx.x * blockDim.x + threadIdx.x;
    if (idx < 2 * Nn) ((int*)g_deg)[idx] = 0;
}

__global__ void hist_kernel(const int* __restrict__ ei1, const int* __restrict__ ei2) {
    int idx = blockIdx.x * blockDim.x + threadIdx.x;
    if (idx >= 2 * EE) return;
    int t = idx >= EE;
    int e = t ? idx - EE : idx;
    const int* ei = t ? ei2 : ei1;
    atomicAdd(&g_deg[t][__ldg(ei + EE + e)], 1);
}

__global__ __launch_bounds__(1024) void scan_kernel() {
    int t = blockIdx.x;
    int tid = threadIdx.x, lane = tid & 31, wid = tid >> 5;
    const int CH = (Nn + 1023) / 1024;   // 49
    int base = tid * CH;
    int hi = min(base + CH, Nn);
    int sum = 0;
    for (int i = base; i < hi; i++) sum += g_deg[t][i];
    int x = sum;
#pragma unroll
    for (int o = 1; o < 32; o <<= 1) {
        int y = __shfl_up_sync(0xffffffff, x, o);
        if (lane >= o) x += y;
    }
    __shared__ int wsum[32];
    if (lane == 31) wsum[wid] = x;
    __syncthreads();
    if (wid == 0) {
        int z = wsum[lane];
#pragma unroll
        for (int o = 1; o < 32; o <<= 1) {
            int y = __shfl_up_sync(0xffffffff, z, o);
            if (lane >= o) z += y;
        }
        wsum[lane] = z;
    }
    __syncthreads();
    int incl = x + (wid > 0 ? wsum[wid - 1] : 0);
    int run = incl - sum;
    for (int i = base; i < hi; i++) {
        int d = g_deg[t][i];
        g_off[t][i] = run;
        g_deg[t][i] = run;   // becomes scatter cursor
        run += d;
    }
    if (tid == 1023) g_off[t][Nn] = incl;
}

__global__ void scatter_kernel(const int* __restrict__ ei1, const float* __restrict__ ev1,
                               const int* __restrict__ ei2, const float* __restrict__ ev2) {
    int idx = blockIdx.x * blockDim.x + threadIdx.x;
    if (idx >= 2 * EE) return;
    int t = idx >= EE;
    int e = t ? idx - EE : idx;
    const int* ei = t ? ei2 : ei1;
    const float* ev = t ? ev2 : ev1;
    int src = __ldg(ei + e);
    int dst = __ldg(ei + EE + e);
    int pos = atomicAdd(&g_deg[t][dst], 1);
    g_esrc[t][pos] = src;
    g_eval[t][pos] = __ldg(ev + e);
}

// ====== fused: spmm1(F=128) + bias + relu + (h @ W2/W4) -> g_hw; 32 rows/block ======
#define SP1_ROWS 32
#define SHPAD    132
__global__ __launch_bounds__(256) void spmm128_gemm2_kernel(const float* __restrict__ b1,
                                                            const float* __restrict__ b3,
                                                            const float* __restrict__ W2,
                                                            const float* __restrict__ W4) {
    __shared__ float sh[SP1_ROWS][SHPAD];   // 16.9 KB
    __shared__ float sW[HH * CC];           // 20 KB
    int t = blockIdx.y;
    const float* W = t ? W4 : W2;
    const float* b = t ? b3 : b1;
    int tid = threadIdx.x;
    for (int i = tid; i < HH * CC; i += 256) sW[i] = W[i];

    int g = tid >> 5, lane = tid & 31;
    int c = lane * 4;
    float4 bv = *(const float4*)(b + c);
    int row0 = blockIdx.x * SP1_ROWS;
    const int*   es  = g_esrc[t];
    const float* evv = g_eval[t];
    const float* feat = g_xw + t * HH + c;

#pragma unroll
    for (int rr = g; rr < SP1_ROWS; rr += 8) {
        int row = row0 + rr;
        if (row >= Nn) break;
        int s0 = __ldg(&g_off[t][row]), s1 = __ldg(&g_off[t][row + 1]);
        float ax = 0.f, ay = 0.f, az = 0.f, aw = 0.f;
        int e = s0;
        for (; e + 4 <= s1; e += 4) {
            int   sA = __ldg(es + e),      sB = __ldg(es + e + 1);
            int   sC = __ldg(es + e + 2),  sD = __ldg(es + e + 3);
            float vA = __ldg(evv + e),     vB = __ldg(evv + e + 1);
            float vC = __ldg(evv + e + 2), vD = __ldg(evv + e + 3);
            float4 fA = *(const float4*)(feat + (size_t)sA * NCAT);
            float4 fB = *(const float4*)(feat + (size_t)sB * NCAT);
            float4 fC = *(const float4*)(feat + (size_t)sC * NCAT);
            float4 fD = *(const float4*)(feat + (size_t)sD * NCAT);
            ax += vA * fA.x + vB * fB.x + vC * fC.x + vD * fD.x;
            ay += vA * fA.y + vB * fB.y + vC * fC.y + vD * fD.y;
            az += vA * fA.z + vB * fB.z + vC * fC.z + vD * fD.z;
            aw += vA * fA.w + vB * fB.w + vC * fC.w + vD * fD.w;
        }
        for (; e < s1; e++) {
            int   sA = __ldg(es + e);
            float vA = __ldg(evv + e);
            float4 fA = *(const float4*)(feat + (size_t)sA * NCAT);
            ax += vA * fA.x; ay += vA * fA.y; az += vA * fA.z; aw += vA * fA.w;
        }
        sh[rr][c + 0] = fmaxf(ax + bv.x, 0.f);
        sh[rr][c + 1] = fmaxf(ay + bv.y, 0.f);
        sh[rr][c + 2] = fmaxf(az + bv.z, 0.f);
        sh[rr][c + 3] = fmaxf(aw + bv.w, 0.f);
    }
    __syncthreads();

#pragma unroll
    for (int oi = tid; oi < SP1_ROWS * CC; oi += 256) {
        int r = oi / CC, cc = oi - r * CC;
        int row = row0 + r;
        if (row >= Nn) continue;
        float acc = 0.f;
        const float4* shr = (const float4*)&sh[r][0];
#pragma unroll
        for (int k4 = 0; k4 < HH / 4; k4++) {
            float4 h = shr[k4];
            int k = k4 * 4;
            acc += h.x * sW[(k + 0) * CC + cc];
            acc += h.y * sW[(k + 1) * CC + cc];
            acc += h.z * sW[(k + 2) * CC + cc];
            acc += h.w * sW[(k + 3) * CC + cc];
        }
        g_hw[t][(size_t)row * CC + cc] = acc;
    }
}

// ====== fused: spmm2(F=40, both towers) + bias + gate + log_softmax -> out; 16 rows/block ======
#define SP2_ROWS 16
__global__ __launch_bounds__(320) void spmm40_fuse_kernel(const float* __restrict__ b2,
                                                          const float* __restrict__ b4,
                                                          const float* __restrict__ Wl,
                                                          const float* __restrict__ bl,
                                                          float* __restrict__ out) {
    __shared__ float sWl[2 * CC * CC];      // 12.8 KB
    __shared__ float sbl[CC];
    __shared__ float so[SP2_ROWS][2 * CC];
    int tid = threadIdx.x;
    for (int i = tid; i < 2 * CC * CC; i += 320) sWl[i] = Wl[i];
    if (tid < CC) sbl[tid] = bl[tid];

    int rl = tid / 20, sub = tid - rl * 20;
    int t = sub / 10, c = (sub - t * 10) * 4;
    int row = blockIdx.x * SP2_ROWS + rl;
    if (row < Nn) {
        int s0 = __ldg(&g_off[t][row]), s1 = __ldg(&g_off[t][row + 1]);
        const int*   es  = g_esrc[t];
        const float* evv = g_eval[t];
        const float* feat = g_hw[t] + c;
        float ax = 0.f, ay = 0.f, az = 0.f, aw = 0.f;
        int e = s0;
        for (; e + 4 <= s1; e += 4) {
            int   sA = __ldg(es + e),      sB = __ldg(es + e + 1);
            int   sC = __ldg(es + e + 2),  sD = __ldg(es + e + 3);
            float vA = __ldg(evv + e),     vB = __ldg(evv + e + 1);
            float vC = __ldg(evv + e + 2), vD = __ldg(evv + e + 3);
            float4 fA = *(const float4*)(feat + (size_t)sA * CC);
            float4 fB = *(const float4*)(feat + (size_t)sB * CC);
            float4 fC = *(const float4*)(feat + (size_t)sC * CC);
            float4 fD = *(const float4*)(feat + (size_t)sD * CC);
            ax += vA * fA.x + vB * fB.x + vC * fC.x + vD * fD.x;
            ay += vA * fA.y + vB * fB.y + vC * fC.y + vD * fD.y;
            az += vA * fA.z + vB * fB.z + vC * fC.z + vD * fD.z;
            aw += vA * fA.w + vB * fB.w + vC * fC.w + vD * fD.w;
        }
        for (; e < s1; e++) {
            int   sA = __ldg(es + e);
            float vA = __ldg(evv + e);
            float4 fA = *(const float4*)(feat + (size_t)sA * CC);
            ax += vA * fA.x; ay += vA * fA.y; az += vA * fA.z; aw += vA * fA.w;
        }
        const float* b = t ? b4 : b2;
        float4 r4;
        r4.x = ax + b[c];     r4.y = ay + b[c + 1];
        r4.z = az + b[c + 2]; r4.w = aw + b[c + 3];
        *(float4*)&so[rl][t * CC + c] = r4;
    }
    __syncthreads();

    int w = tid >> 5, lane = tid & 31;
    if (w < 8) {
#pragma unroll
        for (int rp = 0; rp < 2; rp++) {
            int rl2 = w * 2 + rp;
            int row2 = blockIdx.x * SP2_ROWS + rl2;
            if (row2 >= Nn) continue;
            const float* sr = so[rl2];
            float v0, v1 = -INFINITY;
            {
                int cc = lane;
                float a = sbl[cc];
#pragma unroll
                for (int j = 0; j < 2 * CC; j++) a += sr[j] * sWl[j * CC + cc];
                float gg = 1.f / (1.f + __expf(-a));
                v0 = gg * sr[cc] + (1.f - gg) * sr[CC + cc];
            }
            if (lane < 8) {
                int cc = 32 + lane;
                float a = sbl[cc];
#pragma unroll
                for (int j = 0; j < 2 * CC; j++) a += sr[j] * sWl[j * CC + cc];
                float gg = 1.f / (1.f + __expf(-a));
                v1 = gg * sr[cc] + (1.f - gg) * sr[CC + cc];
            }
            float m = fmaxf(v0, v1);
#pragma unroll
            for (int o = 16; o > 0; o >>= 1) m = fmaxf(m, __shfl_xor_sync(0xffffffff, m, o));
            float s = expf(v0 - m) + (lane < 8 ? expf(v1 - m) : 0.f);
#pragma unroll
            for (int o = 16; o > 0; o >>= 1) s += __shfl_xor_sync(0xffffffff, s, o);
            float lse = m + logf(s);
            out[(size_t)row2 * CC + lane] = v0 - lse;
            if (lane < 8) out[(size_t)row2 * CC + 32 + lane] = v1 - lse;
        }
    }
}

// ---------------- launch ----------------
extern "C" void kernel_launch(void* const* d_in, const int* in_sizes, int n_in,
                              void* d_out, int out_size) {
    const float* x   = (const float*)d_in[0];
    const int*   ei1 = (const int*)  d_in[1];
    const float* ev1 = (const float*)d_in[2];
    const int*   ei2 = (const int*)  d_in[3];
    const float* ev2 = (const float*)d_in[4];
    const float* W1  = (const float*)d_in[5];
    const float* b1  = (const float*)d_in[6];
    const float* W2  = (const float*)d_in[7];
    const float* b2  = (const float*)d_in[8];
    const float* W3  = (const float*)d_in[9];
    const float* b3  = (const float*)d_in[10];
    const float* W4  = (const float*)d_in[11];
    const float* b4  = (const float*)d_in[12];
    const float* Wl  = (const float*)d_in[13];
    const float* bl  = (const float*)d_in[14];
    float* out = (float*)d_out;

    static cudaStream_t s_csr = nullptr;
    static cudaEvent_t ev_fork = nullptr, ev_join = nullptr;
    if (s_csr == nullptr) {
        cudaFuncSetAttribute(sgemm_bf16_kernel, cudaFuncAttributeMaxDynamicSharedMemorySize, S_TOTAL_BYTES);
        cudaStreamCreateWithFlags(&s_csr, cudaStreamNonBlocking);
        cudaEventCreateWithFlags(&ev_fork, cudaEventDisableTiming);
        cudaEventCreateWithFlags(&ev_join, cudaEventDisableTiming);
    }

    // ---- fork: CSR build on side stream, overlapped with dense chain ----
    cudaEventRecord(ev_fork, 0);
    cudaStreamWaitEvent(s_csr, ev_fork, 0);
    zero_deg_kernel<<<(2 * Nn + 255) / 256, 256, 0, s_csr>>>();
    hist_kernel<<<(2 * EE + 255) / 256, 256, 0, s_csr>>>(ei1, ei2);
    scan_kernel<<<2, 1024, 0, s_csr>>>();
    scatter_kernel<<<(2 * EE + 255) / 256, 256, 0, s_csr>>>(ei1, ev1, ei2, ev2);
    cudaEventRecord(ev_join, s_csr);

    // ---- dense chain on main stream (A conversion fused into GEMM) ----
    pack_w_kernel<<<(NCAT * F0 + 255) / 256, 256>>>(W1, W3);
    {
        dim3 g(2, (Nn + 127) / 128);   // bc fast -> A-tile L2 reuse between the pair
        sgemm_bf16_kernel<<<g, 256, S_TOTAL_BYTES>>>(x);
    }

    // ---- join: spmm needs both CSR and g_xw ----
    cudaStreamWaitEvent(0, ev_join, 0);

    // fused spmm1 + bias + relu + gemm2, both towers
    {
        dim3 g((Nn + SP1_ROWS - 1) / SP1_ROWS, 2);
        spmm128_gemm2_kernel<<<g, 256>>>(b1, b3, W2, W4);
    }
    // fused spmm2 + bias + gate + log_softmax (both towers in one kernel)
    {
        dim3 g((Nn + SP2_ROWS - 1) / SP2_ROWS);
        spmm40_fuse_kernel<<<g, 320>>>(b2, b4, Wl, bl, out);
    }
}

// round 16
// speedup vs baseline: 4.5277x; 1.0209x over previous
#include <cuda_runtime.h>
#include <cuda_bf16.h>
#include <math.h>
#include <cstdint>

#define Nn     50000
#define F0     512
#define HH     128
#define CC     40
#define EE     800000
#define NCAT   256   // packed output cols: W1 -> 0..127, W3 -> 128..255

// ---------------- scratch (static device globals; no allocation) ----------------
__device__ __nv_bfloat16 g_Bhi[NCAT * F0];   // [n][k] K-major (transposed Wcat)
__device__ __nv_bfloat16 g_Blo[NCAT * F0];
__device__ float g_xw[(size_t)Nn * NCAT];    // X @ [W1 | W3]
__device__ float g_hw[2][Nn * CC];           // relu(spmm1+b) @ W2/W4
// CSR (dst-binned edges, reused by both spmm layers)
__device__ int   g_deg[2][Nn];               // degree -> cursor (reused)
__device__ int   g_off[2][Nn + 1];
__device__ int   g_esrc[2][EE];
__device__ float g_eval[2][EE];

// ======================= helpers =======================
__device__ __forceinline__ uint32_t smem_to_u32(const void* p) {
    uint32_t a;
    asm("{ .reg .u64 t; cvta.to.shared.u64 t, %1; cvt.u32.u64 %0, t; }" : "=r"(a) : "l"(p));
    return a;
}
__device__ __forceinline__ void cp16(uint32_t dst, const void* src) {
    asm volatile("cp.async.cg.shared.global [%0], [%1], 16;" :: "r"(dst), "l"(src));
}
#define CP_COMMIT() asm volatile("cp.async.commit_group;" ::: "memory")
#define CP_WAIT(n)  asm volatile("cp.async.wait_group %0;" :: "n"(n) : "memory")

#define LDSM4(r0, r1, r2, r3, addr) \
    asm volatile("ldmatrix.sync.aligned.m8n8.x4.shared.b16 {%0,%1,%2,%3}, [%4];" \
                 : "=r"(r0), "=r"(r1), "=r"(r2), "=r"(r3) : "r"(addr))

#define MMA16816(d, a, b) \
    asm volatile("mma.sync.aligned.m16n8k16.row.col.f32.bf16.bf16.f32 " \
                 "{%0,%1,%2,%3}, {%4,%5,%6,%7}, {%8,%9}, {%0,%1,%2,%3};" \
                 : "+f"((d)[0]), "+f"((d)[1]), "+f"((d)[2]), "+f"((d)[3]) \
                 : "r"((a)[0]), "r"((a)[1]), "r"((a)[2]), "r"((a)[3]), \
                   "r"((b)[0]), "r"((b)[1]))

// ---------------- pack W1,W3 transposed into bf16 hi/lo [NCAT][F0] ----------------
__global__ void pack_w_kernel(const float* __restrict__ W1, const float* __restrict__ W3) {
    int idx = blockIdx.x * blockDim.x + threadIdx.x;   // NCAT * F0, k fastest
    if (idx >= NCAT * F0) return;
    int n = idx >> 9, k = idx & (F0 - 1);
    float w = (n < HH) ? W1[k * HH + n] : W3[k * HH + (n - HH)];
    __nv_bfloat16 hi = __float2bfloat16_rn(w);
    g_Bhi[idx] = hi;
    g_Blo[idx] = __float2bfloat16_rn(w - __bfloat162float(hi));
}

// ---------------- bf16 split GEMM via mma.sync, fp32 A converted in-kernel ----------------
// One launch per tower half (bc as param) to enable tower-pipelined overlap with spmm1.
#define SROW      40
#define KCHUNK    32
#define NSTAGE    (F0 / KCHUNK)            // 16
#define A32_STAGE (128 * KCHUNK * 4)       // 16384 B (fp32 A tile)
#define B_MAT     (128 * SROW * 2)         // 10240 B (one bf16 matrix, padded)
#define B_STAGE   (2 * B_MAT)              // 20480 B (Bhi | Blo)
#define SM_A32    0                        // 3 stages: 49152
#define SM_B      (3 * A32_STAGE)          // 3 stages: 61440
#define AH_MAT    B_MAT
#define AH_BUF    (2 * AH_MAT)             // Ahi | Alo = 20480
#define SM_AH     (SM_B + 3 * B_STAGE)     // 2 bufs: 40960
#define S_TOTAL_BYTES (SM_AH + 2 * AH_BUF) // 151552

__device__ __forceinline__ void issue_stage(uint32_t smem_u32, const float* __restrict__ x,
                                            int br, int bc, int slot, int k0) {
    int t = threadIdx.x;
    int row = t >> 1, half = t & 1;
    int koff = half * 16;   // elements
    size_t arow = (size_t)min(br * 128 + row, Nn - 1);
    const float* gx = x + arow * F0 + k0 + koff;
    uint32_t da = smem_u32 + SM_A32 + slot * A32_STAGE + (row * KCHUNK + koff) * 4;
    cp16(da, gx); cp16(da + 16, gx + 4); cp16(da + 32, gx + 8); cp16(da + 48, gx + 12);
    size_t nrow = (size_t)(bc * 128 + row);
    const __nv_bfloat16* gbh = g_Bhi + nrow * F0 + k0 + koff;
    const __nv_bfloat16* gbl = g_Blo + nrow * F0 + k0 + koff;
    uint32_t db = smem_u32 + SM_B + slot * B_STAGE + (row * SROW + koff) * 2;
    cp16(db, gbh); cp16(db + 16, gbh + 8);
    cp16(db + B_MAT, gbl); cp16(db + B_MAT + 16, gbl + 8);
}

__global__ void __launch_bounds__(256, 1) sgemm_bf16_kernel(const float* __restrict__ x, int bc) {
    extern __shared__ char smem[];
    uint32_t smem_u32 = smem_to_u32(smem);
    int tid = threadIdx.x, lane = tid & 31, wid = tid >> 5;
    int wm = wid & 3, wn = wid >> 2;
    int br = blockIdx.x;

    float acc[2][8][4];
#pragma unroll
    for (int i = 0; i < 2; i++)
#pragma unroll
        for (int j = 0; j < 8; j++)
#pragma unroll
            for (int q = 0; q < 4; q++) acc[i][j][q] = 0.f;

    int a_row  = wm * 32 + (lane & 15);
    int a_koff = (lane >> 4) * 8;
    int b_n    = wn * 64 + (lane & 7) + ((lane >> 4) << 3);
    int b_koff = ((lane >> 3) & 1) * 8;

    int cv_row = tid >> 1, cv_half = tid & 1;
    int cv_koff = cv_half * 16;

    issue_stage(smem_u32, x, br, bc, 0, 0);
    CP_COMMIT();
    issue_stage(smem_u32, x, br, bc, 1, KCHUNK);
    CP_COMMIT();

    for (int i = 0; i < NSTAGE; i++) {
        int s3 = i % 3, b2 = i & 1;
        if (i + 2 < NSTAGE) CP_WAIT(1); else CP_WAIT(0);
        __syncthreads();
        if (i + 2 < NSTAGE) {
            issue_stage(smem_u32, x, br, bc, (i + 2) % 3, (i + 2) * KCHUNK);
            CP_COMMIT();
        }
        // convert own fp32 A chunk -> bf16 hi/lo staging buffer
        {
            const float* src = (const float*)(smem + SM_A32 + s3 * A32_STAGE) + cv_row * KCHUNK + cv_koff;
            uint32_t hi8[8], lo8[8];
#pragma unroll
            for (int j = 0; j < 4; j++) {
                float4 v = ((const float4*)src)[j];
                __nv_bfloat16 hx = __float2bfloat16_rn(v.x);
                __nv_bfloat16 hy = __float2bfloat16_rn(v.y);
                __nv_bfloat16 hz = __float2bfloat16_rn(v.z);
                __nv_bfloat16 hw = __float2bfloat16_rn(v.w);
                __nv_bfloat162 ph0 = __halves2bfloat162(hx, hy);
                __nv_bfloat162 ph1 = __halves2bfloat162(hz, hw);
                __nv_bfloat162 pl0 = __halves2bfloat162(
                    __float2bfloat16_rn(v.x - __bfloat162float(hx)),
                    __float2bfloat16_rn(v.y - __bfloat162float(hy)));
                __nv_bfloat162 pl1 = __halves2bfloat162(
                    __float2bfloat16_rn(v.z - __bfloat162float(hz)),
                    __float2bfloat16_rn(v.w - __bfloat162float(hw)));
                hi8[2 * j]     = *(uint32_t*)&ph0;
                hi8[2 * j + 1] = *(uint32_t*)&ph1;
                lo8[2 * j]     = *(uint32_t*)&pl0;
                lo8[2 * j + 1] = *(uint32_t*)&pl1;
            }
            char* dsthi = smem + SM_AH + b2 * AH_BUF + (cv_row * SROW + cv_koff) * 2;
            ((uint4*)dsthi)[0] = make_uint4(hi8[0], hi8[1], hi8[2], hi8[3]);
            ((uint4*)dsthi)[1] = make_uint4(hi8[4], hi8[5], hi8[6], hi8[7]);
            char* dstlo = dsthi + AH_MAT;
            ((uint4*)dstlo)[0] = make_uint4(lo8[0], lo8[1], lo8[2], lo8[3]);
            ((uint4*)dstlo)[1] = make_uint4(lo8[4], lo8[5], lo8[6], lo8[7]);
        }
        __syncthreads();

        uint32_t abase = smem_u32 + SM_AH + b2 * AH_BUF;
        uint32_t bbase = smem_u32 + SM_B + s3 * B_STAGE;
#pragma unroll
        for (int kk = 0; kk < KCHUNK; kk += 16) {
            uint32_t ahi[2][4], alo[2][4];
#pragma unroll
            for (int t = 0; t < 2; t++) {
                uint32_t addr = abase + ((a_row + t * 16) * SROW + kk + a_koff) * 2;
                LDSM4(ahi[t][0], ahi[t][1], ahi[t][2], ahi[t][3], addr);
                LDSM4(alo[t][0], alo[t][1], alo[t][2], alo[t][3], addr + AH_MAT);
            }
            uint32_t bhi[8][2], blo[8][2];
#pragma unroll
            for (int p = 0; p < 4; p++) {
                uint32_t addr = bbase + ((b_n + p * 16) * SROW + kk + b_koff) * 2;
                uint32_t r0, r1, r2, r3;
                LDSM4(r0, r1, r2, r3, addr);
                bhi[2 * p][0] = r0; bhi[2 * p][1] = r1;
                bhi[2 * p + 1][0] = r2; bhi[2 * p + 1][1] = r3;
                LDSM4(r0, r1, r2, r3, addr + B_MAT);
                blo[2 * p][0] = r0; blo[2 * p][1] = r1;
                blo[2 * p + 1][0] = r2; blo[2 * p + 1][1] = r3;
            }
#pragma unroll
            for (int mt = 0; mt < 2; mt++)
#pragma unroll
                for (int nt = 0; nt < 8; nt++) {
                    MMA16816(acc[mt][nt], ahi[mt], bhi[nt]);
                    MMA16816(acc[mt][nt], ahi[mt], blo[nt]);
                    MMA16816(acc[mt][nt], alo[mt], bhi[nt]);
                }
        }
    }

#pragma unroll
    for (int mt = 0; mt < 2; mt++) {
        int r0 = br * 128 + wm * 32 + mt * 16 + (lane >> 2);
        int r1 = r0 + 8;
#pragma unroll
        for (int nt = 0; nt < 8; nt++) {
            int col = bc * 128 + wn * 64 + nt * 8 + (lane & 3) * 2;
            if (r0 < Nn)
                *(float2*)(g_xw + (size_t)r0 * NCAT + col) = make_float2(acc[mt][nt][0], acc[mt][nt][1]);
            if (r1 < Nn)
                *(float2*)(g_xw + (size_t)r1 * NCAT + col) = make_float2(acc[mt][nt][2], acc[mt][nt][3]);
        }
    }
}

// ================= CSR build (per tower; reused by both spmm layers) =================
__global__ void zero_deg_kernel() {
    int idx = blockIdx.x * blockDim.x + threadIdx.x;
    if (idx < 2 * Nn) ((int*)g_deg)[idx] = 0;
}

__global__ void hist_kernel(const int* __restrict__ ei1, const int* __restrict__ ei2) {
    int idx = blockIdx.x * blockDim.x + threadIdx.x;
    if (idx >= 2 * EE) return;
    int t = idx >= EE;
    int e = t ? idx - EE : idx;
    const int* ei = t ? ei2 : ei1;
    atomicAdd(&g_deg[t][__ldg(ei + EE + e)], 1);
}

__global__ __launch_bounds__(1024) void scan_kernel() {
    int t = blockIdx.x;
    int tid = threadIdx.x, lane = tid & 31, wid = tid >> 5;
    const int CH = (Nn + 1023) / 1024;   // 49
    int base = tid * CH;
    int hi = min(base + CH, Nn);
    int sum = 0;
    for (int i = base; i < hi; i++) sum += g_deg[t][i];
    int x = sum;
#pragma unroll
    for (int o = 1; o < 32; o <<= 1) {
        int y = __shfl_up_sync(0xffffffff, x, o);
        if (lane >= o) x += y;
    }
    __shared__ int wsum[32];
    if (lane == 31) wsum[wid] = x;
    __syncthreads();
    if (wid == 0) {
        int z = wsum[lane];
#pragma unroll
        for (int o = 1; o < 32; o <<= 1) {
            int y = __shfl_up_sync(0xffffffff, z, o);
            if (lane >= o) z += y;
        }
        wsum[lane] = z;
    }
    __syncthreads();
    int incl = x + (wid > 0 ? wsum[wid - 1] : 0);
    int run = incl - sum;
    for (int i = base; i < hi; i++) {
        int d = g_deg[t][i];
        g_off[t][i] = run;
        g_deg[t][i] = run;   // becomes scatter cursor
        run += d;
    }
    if (tid == 1023) g_off[t][Nn] = incl;
}

__global__ void scatter_kernel(const int* __restrict__ ei1, const float* __restrict__ ev1,
                               const int* __restrict__ ei2, const float* __restrict__ ev2) {
    int idx = blockIdx.x * blockDim.x + threadIdx.x;
    if (idx >= 2 * EE) return;
    int t = idx >= EE;
    int e = t ? idx - EE : idx;
    const int* ei = t ? ei2 : ei1;
    const float* ev = t ? ev2 : ev1;
    int src = __ldg(ei + e);
    int dst = __ldg(ei + EE + e);
    int pos = atomicAdd(&g_deg[t][dst], 1);
    g_esrc[t][pos] = src;
    g_eval[t][pos] = __ldg(ev + e);
}

// ====== fused: spmm1(F=128) + bias + relu + (h @ W2/W4) -> g_hw; 32 rows/block; per-tower ======
#define SP1_ROWS 32
#define SHPAD    132
__global__ __launch_bounds__(256) void spmm128_gemm2_kernel(int t,
                                                            const float* __restrict__ bb,
                                                            const float* __restrict__ W) {
    __shared__ float sh[SP1_ROWS][SHPAD];   // 16.9 KB
    __shared__ float sW[HH * CC];           // 20 KB
    int tid = threadIdx.x;
    for (int i = tid; i < HH * CC; i += 256) sW[i] = W[i];

    int g = tid >> 5, lane = tid & 31;
    int c = lane * 4;
    float4 bv = *(const float4*)(bb + c);
    int row0 = blockIdx.x * SP1_ROWS;
    const int*   es  = g_esrc[t];
    const float* evv = g_eval[t];
    const float* feat = g_xw + t * HH + c;

#pragma unroll
    for (int rr = g; rr < SP1_ROWS; rr += 8) {
        int row = row0 + rr;
        if (row >= Nn) break;
        int s0 = __ldg(&g_off[t][row]), s1 = __ldg(&g_off[t][row + 1]);
        float ax = 0.f, ay = 0.f, az = 0.f, aw = 0.f;
        int e = s0;
        for (; e + 4 <= s1; e += 4) {
            int   sA = __ldg(es + e),      sB = __ldg(es + e + 1);
            int   sC = __ldg(es + e + 2),  sD = __ldg(es + e + 3);
            float vA = __ldg(evv + e),     vB = __ldg(evv + e + 1);
            float vC = __ldg(evv + e + 2), vD = __ldg(evv + e + 3);
            float4 fA = *(const float4*)(feat + (size_t)sA * NCAT);
            float4 fB = *(const float4*)(feat + (size_t)sB * NCAT);
            float4 fC = *(const float4*)(feat + (size_t)sC * NCAT);
            float4 fD = *(const float4*)(feat + (size_t)sD * NCAT);
            ax += vA * fA.x + vB * fB.x + vC * fC.x + vD * fD.x;
            ay += vA * fA.y + vB * fB.y + vC * fC.y + vD * fD.y;
            az += vA * fA.z + vB * fB.z + vC * fC.z + vD * fD.z;
            aw += vA * fA.w + vB * fB.w + vC * fC.w + vD * fD.w;
        }
        for (; e < s1; e++) {
            int   sA = __ldg(es + e);
            float vA = __ldg(evv + e);
            float4 fA = *(const float4*)(feat + (size_t)sA * NCAT);
            ax += vA * fA.x; ay += vA * fA.y; az += vA * fA.z; aw += vA * fA.w;
        }
        sh[rr][c + 0] = fmaxf(ax + bv.x, 0.f);
        sh[rr][c + 1] = fmaxf(ay + bv.y, 0.f);
        sh[rr][c + 2] = fmaxf(az + bv.z, 0.f);
        sh[rr][c + 3] = fmaxf(aw + bv.w, 0.f);
    }
    __syncthreads();

#pragma unroll
    for (int oi = tid; oi < SP1_ROWS * CC; oi += 256) {
        int r = oi / CC, cc = oi - r * CC;
        int row = row0 + r;
        if (row >= Nn) continue;
        float acc = 0.f;
        const float4* shr = (const float4*)&sh[r][0];
#pragma unroll
        for (int k4 = 0; k4 < HH / 4; k4++) {
            float4 h = shr[k4];
            int k = k4 * 4;
            acc += h.x * sW[(k + 0) * CC + cc];
            acc += h.y * sW[(k + 1) * CC + cc];
            acc += h.z * sW[(k + 2) * CC + cc];
            acc += h.w * sW[(k + 3) * CC + cc];
        }
        g_hw[t][(size_t)row * CC + cc] = acc;
    }
}

// ====== fused: spmm2(F=40, both towers) + bias + gate + log_softmax -> out; 16 rows/block ======
#define SP2_ROWS 16
__global__ __launch_bounds__(320) void spmm40_fuse_kernel(const float* __restrict__ b2,
                                                          const float* __restrict__ b4,
                                                          const float* __restrict__ Wl,
                                                          const float* __restrict__ bl,
                                                          float* __restrict__ out) {
    __shared__ float sWl[2 * CC * CC];      // 12.8 KB
    __shared__ float sbl[CC];
    __shared__ float so[SP2_ROWS][2 * CC];
    int tid = threadIdx.x;
    for (int i = tid; i < 2 * CC * CC; i += 320) sWl[i] = Wl[i];
    if (tid < CC) sbl[tid] = bl[tid];

    int rl = tid / 20, sub = tid - rl * 20;
    int t = sub / 10, c = (sub - t * 10) * 4;
    int row = blockIdx.x * SP2_ROWS + rl;
    if (row < Nn) {
        int s0 = __ldg(&g_off[t][row]), s1 = __ldg(&g_off[t][row + 1]);
        const int*   es  = g_esrc[t];
        const float* evv = g_eval[t];
        const float* feat = g_hw[t] + c;
        float ax = 0.f, ay = 0.f, az = 0.f, aw = 0.f;
        int e = s0;
        for (; e + 4 <= s1; e += 4) {
            int   sA = __ldg(es + e),      sB = __ldg(es + e + 1);
            int   sC = __ldg(es + e + 2),  sD = __ldg(es + e + 3);
            float vA = __ldg(evv + e),     vB = __ldg(evv + e + 1);
            float vC = __ldg(evv + e + 2), vD = __ldg(evv + e + 3);
            float4 fA = *(const float4*)(feat + (size_t)sA * CC);
            float4 fB = *(const float4*)(feat + (size_t)sB * CC);
            float4 fC = *(const float4*)(feat + (size_t)sC * CC);
            float4 fD = *(const float4*)(feat + (size_t)sD * CC);
            ax += vA * fA.x + vB * fB.x + vC * fC.x + vD * fD.x;
            ay += vA * fA.y + vB * fB.y + vC * fC.y + vD * fD.y;
            az += vA * fA.z + vB * fB.z + vC * fC.z + vD * fD.z;
            aw += vA * fA.w + vB * fB.w + vC * fC.w + vD * fD.w;
        }
        for (; e < s1; e++) {
            int   sA = __ldg(es + e);
            float vA = __ldg(evv + e);
            float4 fA = *(const float4*)(feat + (size_t)sA * CC);
            ax += vA * fA.x; ay += vA * fA.y; az += vA * fA.z; aw += vA * fA.w;
        }
        const float* b = t ? b4 : b2;
        float4 r4;
        r4.x = ax + b[c];     r4.y = ay + b[c + 1];
        r4.z = az + b[c + 2]; r4.w = aw + b[c + 3];
        *(float4*)&so[rl][t * CC + c] = r4;
    }
    __syncthreads();

    int w = tid >> 5, lane = tid & 31;
    if (w < 8) {
#pragma unroll
        for (int rp = 0; rp < 2; rp++) {
            int rl2 = w * 2 + rp;
            int row2 = blockIdx.x * SP2_ROWS + rl2;
            if (row2 >= Nn) continue;
            const float* sr = so[rl2];
            float v0, v1 = -INFINITY;
            {
                int cc = lane;
                float a = sbl[cc];
#pragma unroll
                for (int j = 0; j < 2 * CC; j++) a += sr[j] * sWl[j * CC + cc];
                float gg = 1.f / (1.f + __expf(-a));
                v0 = gg * sr[cc] + (1.f - gg) * sr[CC + cc];
            }
            if (lane < 8) {
                int cc = 32 + lane;
                float a = sbl[cc];
#pragma unroll
                for (int j = 0; j < 2 * CC; j++) a += sr[j] * sWl[j * CC + cc];
                float gg = 1.f / (1.f + __expf(-a));
                v1 = gg * sr[cc] + (1.f - gg) * sr[CC + cc];
            }
            float m = fmaxf(v0, v1);
#pragma unroll
            for (int o = 16; o > 0; o >>= 1) m = fmaxf(m, __shfl_xor_sync(0xffffffff, m, o));
            float s = expf(v0 - m) + (lane < 8 ? expf(v1 - m) : 0.f);
#pragma unroll
            for (int o = 16; o > 0; o >>= 1) s += __shfl_xor_sync(0xffffffff, s, o);
            float lse = m + logf(s);
            out[(size_t)row2 * CC + lane] = v0 - lse;
            if (lane < 8) out[(size_t)row2 * CC + 32 + lane] = v1 - lse;
        }
    }
}

// ---------------- launch ----------------
extern "C" void kernel_launch(void* const* d_in, const int* in_sizes, int n_in,
                              void* d_out, int out_size) {
    const float* x   = (const float*)d_in[0];
    const int*   ei1 = (const int*)  d_in[1];
    const float* ev1 = (const float*)d_in[2];
    const int*   ei2 = (const int*)  d_in[3];
    const float* ev2 = (const float*)d_in[4];
    const float* W1  = (const float*)d_in[5];
    const float* b1  = (const float*)d_in[6];
    const float* W2  = (const float*)d_in[7];
    const float* b2  = (const float*)d_in[8];
    const float* W3  = (const float*)d_in[9];
    const float* b3  = (const float*)d_in[10];
    const float* W4  = (const float*)d_in[11];
    const float* b4  = (const float*)d_in[12];
    const float* Wl  = (const float*)d_in[13];
    const float* bl  = (const float*)d_in[14];
    float* out = (float*)d_out;

    static cudaStream_t s_side = nullptr;
    static cudaEvent_t ev_fork = nullptr, ev_g0 = nullptr, ev_s0 = nullptr;
    if (s_side == nullptr) {
        cudaFuncSetAttribute(sgemm_bf16_kernel, cudaFuncAttributeMaxDynamicSharedMemorySize, S_TOTAL_BYTES);
        cudaStreamCreateWithFlags(&s_side, cudaStreamNonBlocking);
        cudaEventCreateWithFlags(&ev_fork, cudaEventDisableTiming);
        cudaEventCreateWithFlags(&ev_g0, cudaEventDisableTiming);
        cudaEventCreateWithFlags(&ev_s0, cudaEventDisableTiming);
    }
    static cudaEvent_t ev_join = nullptr;
    if (ev_join == nullptr) cudaEventCreateWithFlags(&ev_join, cudaEventDisableTiming);

    const int GGRID = (Nn + 127) / 128;

    // ---- fork: CSR build on side stream ----
    cudaEventRecord(ev_fork, 0);
    cudaStreamWaitEvent(s_side, ev_fork, 0);
    zero_deg_kernel<<<(2 * Nn + 255) / 256, 256, 0, s_side>>>();
    hist_kernel<<<(2 * EE + 255) / 256, 256, 0, s_side>>>(ei1, ei2);
    scan_kernel<<<2, 1024, 0, s_side>>>();
    scatter_kernel<<<(2 * EE + 255) / 256, 256, 0, s_side>>>(ei1, ev1, ei2, ev2);
    cudaEventRecord(ev_join, s_side);

    // ---- main: pack + GEMM tower 0 ----
    pack_w_kernel<<<(NCAT * F0 + 255) / 256, 256>>>(W1, W3);
    sgemm_bf16_kernel<<<GGRID, 256, S_TOTAL_BYTES>>>(x, 0);
    cudaEventRecord(ev_g0, 0);

    // ---- side: spmm1 tower 0 (needs CSR [program order] + GEMM t0) ----
    cudaStreamWaitEvent(s_side, ev_g0, 0);
    {
        dim3 g((Nn + SP1_ROWS - 1) / SP1_ROWS);
        spmm128_gemm2_kernel<<<g, 256, 0, s_side>>>(0, b1, W2);
    }
    cudaEventRecord(ev_s0, s_side);

    // ---- main: GEMM tower 1 (concurrent with spmm1 t0) ----
    sgemm_bf16_kernel<<<GGRID, 256, S_TOTAL_BYTES>>>(x, 1);

    // ---- main: spmm1 tower 1 (needs CSR join) ----
    cudaStreamWaitEvent(0, ev_join, 0);
    {
        dim3 g((Nn + SP1_ROWS - 1) / SP1_ROWS);
        spmm128_gemm2_kernel<<<g, 256>>>(1, b3, W4);
    }

    // ---- main: final fused kernel (needs both towers' g_hw) ----
    cudaStreamWaitEvent(0, ev_s0, 0);
    {
        dim3 g((Nn + SP2_ROWS - 1) / SP2_ROWS);
        spmm40_fuse_kernel<<<g, 320>>>(b2, b4, Wl, bl, out);
    }
}